// round 6
// baseline (speedup 1.0000x reference)
#include <cuda_runtime.h>
#include <cstdint>

#define T_ 128
#define B_ 512
#define H_ 128
#define EMBD 300
#define D_ 256
#define G3 384
#define M_ (T_*B_)

__device__ float g_Pf[(size_t)M_*G3];
__device__ float g_Pb[(size_t)M_*G3];
__device__ float g_f[(size_t)M_*D_];
__device__ float g_hyp[(size_t)M_*D_];
__device__ float g_coef[M_];
__device__ float g_q[M_];

typedef unsigned long long ull;
__device__ __forceinline__ void fma2(ull&c, ull a, ull b){ asm("fma.rn.f32x2 %0,%1,%2,%0;":"+l"(c):"l"(a),"l"(b)); }
__device__ __forceinline__ ull pk2(float lo,float hi){ ull r; asm("mov.b64 %0,{%1,%2};":"=l"(r):"f"(lo),"f"(hi)); return r; }
__device__ __forceinline__ float2 upk2(ull v){ float2 r; asm("mov.b64 {%0,%1},%2;":"=f"(r.x),"=f"(r.y):"l"(v)); return r; }

// K1: embed gather + input projection. C[m][n]=emb[tok[m]].W[n]+b, M=65536,K=300,N=768
__global__ __launch_bounds__(256) void k1_embed_proj(
    const int* __restrict__ tok, const float* __restrict__ emb,
    const float* __restrict__ Wf, const float* __restrict__ Wb,
    const float* __restrict__ bf, const float* __restrict__ bb)
{
    __shared__ float As[16][132];
    __shared__ float Bs[16][132];
    __shared__ int toks[128];
    const int tid = threadIdx.x;
    const int bm = blockIdx.x*128, bn = blockIdx.y*128;
    if (tid < 128) toks[tid] = tok[bm+tid];
    __syncthreads();

    ull acc[8][4];
    #pragma unroll
    for (int i=0;i<8;i++){ acc[i][0]=0; acc[i][1]=0; acc[i][2]=0; acc[i][3]=0; }

    const int rl = tid>>1, ks = (tid&1)*8;
    const float* arow = emb + (size_t)toks[rl]*EMBD;
    const int ng = bn + rl;
    const float* wrow = (ng < G3) ? (Wf + (size_t)ng*EMBD) : (Wb + (size_t)(ng-G3)*EMBD);
    const int tm0 = (tid>>4)*8, tn0 = (tid&15)*8;

    for (int kt=0; kt<19; kt++) {
        const int k0 = kt*16;
        if (kt < 18) {
            float4 a0 = *(const float4*)(arow+k0+ks);
            float4 a1 = *(const float4*)(arow+k0+ks+4);
            float4 w0 = *(const float4*)(wrow+k0+ks);
            float4 w1 = *(const float4*)(wrow+k0+ks+4);
            As[ks+0][rl]=a0.x; As[ks+1][rl]=a0.y; As[ks+2][rl]=a0.z; As[ks+3][rl]=a0.w;
            As[ks+4][rl]=a1.x; As[ks+5][rl]=a1.y; As[ks+6][rl]=a1.z; As[ks+7][rl]=a1.w;
            Bs[ks+0][rl]=w0.x; Bs[ks+1][rl]=w0.y; Bs[ks+2][rl]=w0.z; Bs[ks+3][rl]=w0.w;
            Bs[ks+4][rl]=w1.x; Bs[ks+5][rl]=w1.y; Bs[ks+6][rl]=w1.z; Bs[ks+7][rl]=w1.w;
        } else {
            #pragma unroll
            for (int i=0;i<8;i++) {
                int k = k0+ks+i;
                As[ks+i][rl] = (k<EMBD)? arow[k] : 0.f;
                Bs[ks+i][rl] = (k<EMBD)? wrow[k] : 0.f;
            }
        }
        __syncthreads();
        #pragma unroll
        for (int k=0;k<16;k++) {
            float4 a0 = *(const float4*)&As[k][tm0];
            float4 a1 = *(const float4*)&As[k][tm0+4];
            float4 b0 = *(const float4*)&Bs[k][tn0];
            float4 b1 = *(const float4*)&Bs[k][tn0+4];
            ull bp[4] = { pk2(b0.x,b0.y), pk2(b0.z,b0.w), pk2(b1.x,b1.y), pk2(b1.z,b1.w) };
            float av[8] = { a0.x,a0.y,a0.z,a0.w,a1.x,a1.y,a1.z,a1.w };
            #pragma unroll
            for (int i=0;i<8;i++) {
                ull ad = pk2(av[i],av[i]);
                fma2(acc[i][0],ad,bp[0]); fma2(acc[i][1],ad,bp[1]);
                fma2(acc[i][2],ad,bp[2]); fma2(acc[i][3],ad,bp[3]);
            }
        }
        __syncthreads();
    }
    float* dst; int nbase; const float* bias;
    if (bn < G3) { dst=g_Pf; nbase=bn; bias=bf; } else { dst=g_Pb; nbase=bn-G3; bias=bb; }
    float bcol[8];
    #pragma unroll
    for (int j=0;j<8;j++) bcol[j] = bias[nbase+tn0+j];
    #pragma unroll
    for (int i=0;i<8;i++) {
        float2* o = (float2*)(dst + (size_t)(bm+tm0+i)*G3 + nbase + tn0);
        #pragma unroll
        for (int j=0;j<4;j++) { float2 v=upk2(acc[i][j]); v.x+=bcol[2*j]; v.y+=bcol[2*j+1]; o[j]=v; }
    }
}

// K2: GRU both dirs. grid(64,2), 128 threads. W_hh transposed in smem for all steps.
__global__ __launch_bounds__(128) void k2_gru(
    const float* __restrict__ hidden,
    const float* __restrict__ Whf, const float* __restrict__ Whb,
    const float* __restrict__ bhf, const float* __restrict__ bhb,
    float* __restrict__ outH)
{
    extern __shared__ float sm[];
    float* ws = sm;               // [k][j] stride G3, ws[k*G3+j] = W[j][k]
    float* hs = sm + 128*G3;      // [k][bi] stride 8
    const int dir = blockIdx.y, b0 = blockIdx.x*8, t = threadIdx.x;
    const float* W = dir? Whb : Whf;
    const float* bh = dir? bhb : bhf;
    const float* P = dir? g_Pb : g_Pf;

    #pragma unroll
    for (int off=0; off<G3; off+=H_)
        for (int k=0;k<H_;k++) ws[k*G3 + off + t] = W[(size_t)(off+t)*H_ + k];

    float hreg[8];
    #pragma unroll
    for (int bi=0;bi<8;bi++){
        float hv = hidden[(size_t)dir*B_*H_ + (size_t)(b0+bi)*H_ + t];
        hreg[bi]=hv; hs[t*8+bi]=hv;
    }
    const float br=bh[t], bz=bh[H_+t], bn2=bh[2*H_+t];
    __syncthreads();
    const ull* h64 = (const ull*)hs;

    for (int s=0;s<T_;s++){
        const int tt = dir ? (T_-1-s) : s;
        const float* prow = P + ((size_t)tt*B_ + b0)*G3;
        float xr[8],xz[8],xn[8];
        #pragma unroll
        for (int bi=0;bi<8;bi++){
            xr[bi]=prow[bi*G3+t]; xz[bi]=prow[bi*G3+H_+t]; xn[bi]=prow[bi*G3+2*H_+t];
        }
        ull ar[4],az[4],an[4];
        { ull pr=pk2(br,br), pz=pk2(bz,bz), pn=pk2(bn2,bn2);
          #pragma unroll
          for (int p=0;p<4;p++){ ar[p]=pr; az[p]=pz; an[p]=pn; } }
        #pragma unroll 4
        for (int k=0;k<H_;k++){
            const float* wk = ws + k*G3 + t;
            float w0=wk[0], w1=wk[H_], w2=wk[2*H_];
            ull p0=pk2(w0,w0), p1=pk2(w1,w1), p2=pk2(w2,w2);
            #pragma unroll
            for (int p=0;p<4;p++){
                ull hp = h64[k*4+p];
                fma2(ar[p],hp,p0); fma2(az[p],hp,p1); fma2(an[p],hp,p2);
            }
        }
        __syncthreads();
        #pragma unroll
        for (int p=0;p<4;p++){
            float2 gr=upk2(ar[p]), gz=upk2(az[p]), gn=upk2(an[p]);
            #pragma unroll
            for (int l=0;l<2;l++){
                int bi = 2*p+l;
                float r = 1.f/(1.f+expf(-(xr[bi] + (l?gr.y:gr.x))));
                float z = 1.f/(1.f+expf(-(xz[bi] + (l?gz.y:gz.x))));
                float n = tanhf(xn[bi] + r*(l?gn.y:gn.x));
                float h2 = (1.f-z)*n + z*hreg[bi];
                hreg[bi]=h2; hs[t*8+bi]=h2;
                g_f[((size_t)tt*B_ + (b0+bi))*D_ + dir*H_ + t] = h2;
            }
        }
        __syncthreads();
    }
    #pragma unroll
    for (int bi=0;bi<8;bi++)
        outH[(size_t)dir*B_*H_ + (size_t)(b0+bi)*H_ + t] = hreg[bi];
}

// K3: hyp = tanh(f @ AW^T + Ab), M=65536,K=256,N=256
__global__ __launch_bounds__(256) void k3_gemm(const float* __restrict__ AW, const float* __restrict__ Ab)
{
    __shared__ float As[16][132];
    __shared__ float Bs[16][132];
    const int tid=threadIdx.x, bm=blockIdx.x*128, bn=blockIdx.y*128;
    ull acc[8][4];
    #pragma unroll
    for (int i=0;i<8;i++){ acc[i][0]=0; acc[i][1]=0; acc[i][2]=0; acc[i][3]=0; }
    const int rl=tid>>1, ks=(tid&1)*8;
    const float* arow = g_f + (size_t)(bm+rl)*D_;
    const float* wrow = AW + (size_t)(bn+rl)*D_;
    const int tm0=(tid>>4)*8, tn0=(tid&15)*8;

    for (int kt=0; kt<16; kt++){
        const int k0 = kt*16;
        float4 a0=*(const float4*)(arow+k0+ks);
        float4 a1=*(const float4*)(arow+k0+ks+4);
        float4 w0=*(const float4*)(wrow+k0+ks);
        float4 w1=*(const float4*)(wrow+k0+ks+4);
        As[ks+0][rl]=a0.x; As[ks+1][rl]=a0.y; As[ks+2][rl]=a0.z; As[ks+3][rl]=a0.w;
        As[ks+4][rl]=a1.x; As[ks+5][rl]=a1.y; As[ks+6][rl]=a1.z; As[ks+7][rl]=a1.w;
        Bs[ks+0][rl]=w0.x; Bs[ks+1][rl]=w0.y; Bs[ks+2][rl]=w0.z; Bs[ks+3][rl]=w0.w;
        Bs[ks+4][rl]=w1.x; Bs[ks+5][rl]=w1.y; Bs[ks+6][rl]=w1.z; Bs[ks+7][rl]=w1.w;
        __syncthreads();
        #pragma unroll
        for (int k=0;k<16;k++){
            float4 a0v=*(const float4*)&As[k][tm0];
            float4 a1v=*(const float4*)&As[k][tm0+4];
            float4 b0v=*(const float4*)&Bs[k][tn0];
            float4 b1v=*(const float4*)&Bs[k][tn0+4];
            ull bp[4] = { pk2(b0v.x,b0v.y), pk2(b0v.z,b0v.w), pk2(b1v.x,b1v.y), pk2(b1v.z,b1v.w) };
            float av[8] = { a0v.x,a0v.y,a0v.z,a0v.w,a1v.x,a1v.y,a1v.z,a1v.w };
            #pragma unroll
            for (int i=0;i<8;i++){
                ull ad=pk2(av[i],av[i]);
                fma2(acc[i][0],ad,bp[0]); fma2(acc[i][1],ad,bp[1]);
                fma2(acc[i][2],ad,bp[2]); fma2(acc[i][3],ad,bp[3]);
            }
        }
        __syncthreads();
    }
    #pragma unroll
    for (int i=0;i<8;i++){
        float* o = g_hyp + (size_t)(bm+tm0+i)*D_ + bn + tn0;
        #pragma unroll
        for (int j=0;j<4;j++){
            float2 v=upk2(acc[i][j]);
            o[2*j]   = tanhf(v.x + Ab[bn+tn0+2*j]);
            o[2*j+1] = tanhf(v.y + Ab[bn+tn0+2*j+1]);
        }
    }
}

// K4: per-row (t,b): coef = exp(-beta*dist)*gamma, q = tanh(||f||)/||f||
__global__ __launch_bounds__(256) void k4_rows(const float* __restrict__ cent, const float* __restrict__ beta)
{
    __shared__ float swr[8];
    __shared__ float s_cu, s_suru, s_b;
    const int tid = threadIdx.x;
    { float c = cent[tid]; float v=c*c;
      #pragma unroll
      for (int o=16;o;o>>=1) v += __shfl_xor_sync(0xffffffffu, v, o);
      if ((tid&31)==0) swr[tid>>5]=v; }
    __syncthreads();
    if (tid==0){
        float s=0;
        #pragma unroll
        for (int i=0;i<8;i++) s+=swr[i];
        float ru = sqrtf(s);
        s_cu = coshf(ru); s_suru = sinhf(ru)/ru; s_b = beta[0];
    }
    __syncthreads();
    const int w=tid>>5, lane=tid&31;
    const size_t m = (size_t)blockIdx.x*8 + w;
    const float* hr = g_hyp + m*D_;
    const float* fr = g_f + m*D_;
    float s1=0,s2=0,s3=0;
    #pragma unroll
    for (int i=0;i<8;i++){
        int idx = lane + 32*i;
        float hv=hr[idx], fv=fr[idx];
        s1 += hv*cent[idx]; s2 += hv*hv; s3 += fv*fv;
    }
    #pragma unroll
    for (int o=16;o;o>>=1){
        s1 += __shfl_xor_sync(0xffffffffu,s1,o);
        s2 += __shfl_xor_sync(0xffffffffu,s2,o);
        s3 += __shfl_xor_sync(0xffffffffu,s3,o);
    }
    if (lane==0){
        float rr = sqrtf(s2);
        float x = coshf(rr)*s_cu - (sinhf(rr)/rr)*s_suru*s1;
        x = fminf(fmaxf(x, 1.f+1e-7f), 1e16f);
        float dist = logf(x) + log1pf(sqrtf(x*x - 1.f + 1e-7f)/x);
        float rf = sqrtf(s3);
        float th = tanhf(rf);
        float gsq = 1.f - th*th;
        gsq = fminf(fmaxf(gsq, 1e-7f), 1.f-1e-7f);
        float gam = 1.f/sqrtf(gsq);
        gam = fminf(fmaxf(gam, 1.f+1e-7f), 1e16f);
        g_coef[m] = expf(-s_b*dist)*gam;
        g_q[m] = th/rf;
    }
}

// K5: out[b][d] = sum_t coef*q*f / sum_t coef. grid=B, 256 threads.
__global__ __launch_bounds__(256) void k5_pool(float* __restrict__ out)
{
    __shared__ float cq[T_];
    __shared__ float sden;
    const int b = blockIdx.x, tid = threadIdx.x;
    if (tid < T_) cq[tid] = g_coef[tid*B_ + b];
    __syncthreads();
    if (tid==0){ float s=0; for (int t2=0;t2<T_;t2++) s+=cq[t2]; sden=s; }
    __syncthreads();
    if (tid < T_) cq[tid] = cq[tid]*g_q[tid*B_ + b]/sden;
    __syncthreads();
    float acc = 0.f;
    for (int t2=0;t2<T_;t2++)
        acc += cq[t2]*g_f[((size_t)t2*B_ + b)*D_ + tid];
    out[(size_t)b*D_ + tid] = acc;
}

extern "C" void kernel_launch(void* const* d_in, const int* in_sizes, int n_in,
                              void* d_out, int out_size)
{
    const int*   tok  = (const int*)d_in[0];
    const float* hid  = (const float*)d_in[1];
    const float* emb  = (const float*)d_in[2];
    const float* Wif  = (const float*)d_in[3];
    const float* Whf  = (const float*)d_in[4];
    const float* bif  = (const float*)d_in[5];
    const float* bhf  = (const float*)d_in[6];
    const float* Wib  = (const float*)d_in[7];
    const float* Whb  = (const float*)d_in[8];
    const float* bib  = (const float*)d_in[9];
    const float* bhb  = (const float*)d_in[10];
    const float* AW   = (const float*)d_in[11];
    const float* Ab   = (const float*)d_in[12];
    const float* cent = (const float*)d_in[13];
    const float* beta = (const float*)d_in[14];
    float* out = (float*)d_out;

    const int k2smem = 128*G3*4 + 128*8*4;
    cudaFuncSetAttribute(k2_gru, cudaFuncAttributeMaxDynamicSharedMemorySize, k2smem);

    k1_embed_proj<<<dim3(512,6),256>>>(tok, emb, Wif, Wib, bif, bib);
    k2_gru<<<dim3(64,2),128,k2smem>>>(hid, Whf, Whb, bhf, bhb, out + (size_t)B_*D_);
    k3_gemm<<<dim3(512,2),256>>>(AW, Ab);
    k4_rows<<<8192,256>>>(cent, beta);
    k5_pool<<<512,256>>>(out);
}

// round 7
// speedup vs baseline: 1.1687x; 1.1687x over previous
#include <cuda_runtime.h>
#include <cstdint>

#define T_ 128
#define B_ 512
#define H_ 128
#define EMBD 300
#define D_ 256
#define G3 384
#define M_ (T_*B_)

__device__ float g_Pf[(size_t)M_*G3];
__device__ float g_Pb[(size_t)M_*G3];
__device__ float g_f[(size_t)M_*D_];
__device__ float g_s1p[2*M_];
__device__ float g_s2p[2*M_];
__device__ float g_s3[M_];
__device__ float g_coef[M_];
__device__ float g_q[M_];

typedef unsigned long long ull;
__device__ __forceinline__ void fma2(ull&c, ull a, ull b){ asm("fma.rn.f32x2 %0,%1,%2,%0;":"+l"(c):"l"(a),"l"(b)); }
__device__ __forceinline__ void add2(ull&c, ull a){ asm("add.rn.f32x2 %0,%0,%1;":"+l"(c):"l"(a)); }
__device__ __forceinline__ ull pk2(float lo,float hi){ ull r; asm("mov.b64 %0,{%1,%2};":"=l"(r):"f"(lo),"f"(hi)); return r; }
__device__ __forceinline__ float2 upk2(ull v){ float2 r; asm("mov.b64 {%0,%1},%2;":"=f"(r.x),"=f"(r.y):"l"(v)); return r; }

__device__ __forceinline__ float fsigm(float x){ return __fdividef(1.f, 1.f + __expf(-x)); }
__device__ __forceinline__ float ftanh(float x){ float e = __expf(2.f*x); return 1.f - __fdividef(2.f, e + 1.f); }

// shared 128x128x16 tile compute, 8x8 microtile, FFMA2
__device__ __forceinline__ void gemm_tile(ull acc[8][4], const float (*As)[132], const float (*Bs)[132], int tm0, int tn0)
{
    #pragma unroll
    for (int k=0;k<16;k++){
        float4 a0=*(const float4*)&As[k][tm0];
        float4 a1=*(const float4*)&As[k][tm0+4];
        float4 b0=*(const float4*)&Bs[k][tn0];
        float4 b1=*(const float4*)&Bs[k][tn0+4];
        ull bp0=pk2(b0.x,b0.y), bp1=pk2(b0.z,b0.w), bp2=pk2(b1.x,b1.y), bp3=pk2(b1.z,b1.w);
        float av[8] = { a0.x,a0.y,a0.z,a0.w,a1.x,a1.y,a1.z,a1.w };
        #pragma unroll
        for (int i=0;i<8;i++){
            ull ad=pk2(av[i],av[i]);
            fma2(acc[i][0],ad,bp0); fma2(acc[i][1],ad,bp1);
            fma2(acc[i][2],ad,bp2); fma2(acc[i][3],ad,bp3);
        }
    }
}

// ================= K1: embed gather + input projection (M=65536,K=300,N=768) =================
__device__ __forceinline__ void k1_load(const float* __restrict__ arow, const float* __restrict__ wrow,
                                        int kt, int ks, float* a8, float* w8)
{
    const int k0 = kt*16 + ks;
    if (kt < 18){
        float4 a0=*(const float4*)(arow+k0);
        float4 a1=*(const float4*)(arow+k0+4);
        float4 w0=*(const float4*)(wrow+k0);
        float4 w1=*(const float4*)(wrow+k0+4);
        a8[0]=a0.x;a8[1]=a0.y;a8[2]=a0.z;a8[3]=a0.w;a8[4]=a1.x;a8[5]=a1.y;a8[6]=a1.z;a8[7]=a1.w;
        w8[0]=w0.x;w8[1]=w0.y;w8[2]=w0.z;w8[3]=w0.w;w8[4]=w1.x;w8[5]=w1.y;w8[6]=w1.z;w8[7]=w1.w;
    } else {
        #pragma unroll
        for (int i=0;i<8;i++){
            int k = k0+i; bool ok = k<EMBD;
            a8[i] = ok? arow[k] : 0.f;
            w8[i] = ok? wrow[k] : 0.f;
        }
    }
}

__global__ __launch_bounds__(256) void k1_embed_proj(
    const int* __restrict__ tok, const float* __restrict__ emb,
    const float* __restrict__ Wf, const float* __restrict__ Wb,
    const float* __restrict__ bf, const float* __restrict__ bb)
{
    __shared__ float As[2][16][132];
    __shared__ float Bs[2][16][132];
    __shared__ int toks[128];
    const int tid = threadIdx.x;
    const int bm = blockIdx.x*128, bn = blockIdx.y*128;
    if (tid < 128) toks[tid] = tok[bm+tid];
    __syncthreads();

    ull acc[8][4];
    #pragma unroll
    for (int i=0;i<8;i++){ acc[i][0]=0; acc[i][1]=0; acc[i][2]=0; acc[i][3]=0; }

    const int rl = tid>>1, ks = (tid&1)*8;
    const float* arow = emb + (size_t)toks[rl]*EMBD;
    const int ng = bn + rl;
    const float* wrow = (ng < G3) ? (Wf + (size_t)ng*EMBD) : (Wb + (size_t)(ng-G3)*EMBD);
    const int tm0 = (tid>>4)*8, tn0 = (tid&15)*8;

    float a8[8], w8[8];
    k1_load(arow, wrow, 0, ks, a8, w8);
    #pragma unroll
    for (int i=0;i<8;i++){ As[0][ks+i][rl]=a8[i]; Bs[0][ks+i][rl]=w8[i]; }
    __syncthreads();

    for (int kt=0; kt<19; kt++){
        const int cur = kt&1;
        if (kt < 18) k1_load(arow, wrow, kt+1, ks, a8, w8);
        gemm_tile(acc, As[cur], Bs[cur], tm0, tn0);
        if (kt < 18){
            #pragma unroll
            for (int i=0;i<8;i++){ As[cur^1][ks+i][rl]=a8[i]; Bs[cur^1][ks+i][rl]=w8[i]; }
        }
        __syncthreads();
    }

    float* dst; int nbase; const float* bias;
    if (bn < G3) { dst=g_Pf; nbase=bn; bias=bf; } else { dst=g_Pb; nbase=bn-G3; bias=bb; }
    float bcol[8];
    #pragma unroll
    for (int j=0;j<8;j++) bcol[j] = bias[nbase+tn0+j];
    #pragma unroll
    for (int i=0;i<8;i++){
        float2* o = (float2*)(dst + (size_t)(bm+tm0+i)*G3 + nbase + tn0);
        #pragma unroll
        for (int j=0;j<4;j++){ float2 v=upk2(acc[i][j]); v.x+=bcol[2*j]; v.y+=bcol[2*j+1]; o[j]=v; }
    }
}

// ================= K2: bidirectional GRU, grid(64,2), 256 threads (2 k-slices) =================
__global__ __launch_bounds__(256) void k2_gru(
    const float* __restrict__ hidden,
    const float* __restrict__ Whf, const float* __restrict__ Whb,
    const float* __restrict__ bhf, const float* __restrict__ bhb,
    float* __restrict__ outH)
{
    extern __shared__ float sm[];
    float* ws = sm;                                  // [k][j] stride G3: ws[k*G3+j] = W[j][k]
    float* hs = sm + 128*G3;                         // [k][bi] stride 8
    ull*   pbuf = (ull*)(sm + 128*G3 + 128*8);       // [t][12] partials from half 1

    const int dir = blockIdx.y, b0 = blockIdx.x*8;
    const int tid = threadIdx.x;
    const int t = tid & 127;
    const int half = tid >> 7;
    const int kbase = half * 64;
    const float* W  = dir? Whb : Whf;
    const float* bh = dir? bhb : bhf;
    const float* P  = dir? g_Pb : g_Pf;

    for (int idx = tid; idx < 128*G3; idx += 256){
        int j = idx >> 7, k = idx & 127;
        ws[k*G3 + j] = W[(size_t)j*H_ + k];
    }

    float hreg[8];
    if (half == 0){
        #pragma unroll
        for (int bi=0;bi<8;bi++){
            float hv = hidden[(size_t)dir*B_*H_ + (size_t)(b0+bi)*H_ + t];
            hreg[bi]=hv; hs[t*8+bi]=hv;
        }
    }
    const float br=bh[t], bz=bh[H_+t], bn2=bh[2*H_+t];
    __syncthreads();
    const ull* h64 = (const ull*)hs;

    for (int s=0;s<T_;s++){
        const int tt = dir ? (T_-1-s) : s;
        float xr[8],xz[8],xn[8];
        if (half == 0){
            const float* prow = P + ((size_t)tt*B_ + b0)*G3;
            #pragma unroll
            for (int bi=0;bi<8;bi++){
                xr[bi]=prow[bi*G3+t]; xz[bi]=prow[bi*G3+H_+t]; xn[bi]=prow[bi*G3+2*H_+t];
            }
        }
        ull ar[4],az[4],an[4];
        if (half == 0){
            ull pr=pk2(br,br), pz=pk2(bz,bz), pn=pk2(bn2,bn2);
            #pragma unroll
            for (int p=0;p<4;p++){ ar[p]=pr; az[p]=pz; an[p]=pn; }
        } else {
            #pragma unroll
            for (int p=0;p<4;p++){ ar[p]=0; az[p]=0; an[p]=0; }
        }
        #pragma unroll 4
        for (int k=kbase; k<kbase+64; k++){
            const float* wk = ws + k*G3 + t;
            float w0=wk[0], w1=wk[H_], w2=wk[2*H_];
            ull p0=pk2(w0,w0), p1=pk2(w1,w1), p2=pk2(w2,w2);
            #pragma unroll
            for (int p=0;p<4;p++){
                ull hp = h64[k*4+p];
                fma2(ar[p],hp,p0); fma2(az[p],hp,p1); fma2(an[p],hp,p2);
            }
        }
        if (half == 1){
            #pragma unroll
            for (int p=0;p<4;p++){ pbuf[t*12+p]=ar[p]; pbuf[t*12+4+p]=az[p]; pbuf[t*12+8+p]=an[p]; }
        }
        __syncthreads();
        if (half == 0){
            #pragma unroll
            for (int p=0;p<4;p++){ add2(ar[p],pbuf[t*12+p]); add2(az[p],pbuf[t*12+4+p]); add2(an[p],pbuf[t*12+8+p]); }
            #pragma unroll
            for (int p=0;p<4;p++){
                float2 gr=upk2(ar[p]), gz=upk2(az[p]), gn=upk2(an[p]);
                #pragma unroll
                for (int l=0;l<2;l++){
                    int bi = 2*p+l;
                    float r = fsigm(xr[bi] + (l?gr.y:gr.x));
                    float z = fsigm(xz[bi] + (l?gz.y:gz.x));
                    float n = ftanh(xn[bi] + r*(l?gn.y:gn.x));
                    float h2 = (1.f-z)*n + z*hreg[bi];
                    hreg[bi]=h2; hs[t*8+bi]=h2;
                    g_f[((size_t)tt*B_ + (b0+bi))*D_ + dir*H_ + t] = h2;
                }
            }
        }
        __syncthreads();
    }
    if (half == 0){
        #pragma unroll
        for (int bi=0;bi<8;bi++)
            outH[(size_t)dir*B_*H_ + (size_t)(b0+bi)*H_ + t] = hreg[bi];
    }
}

// ============ K3: hyp=tanh(f@AW^T+Ab) fused with per-row reductions (no hyp store) ============
__global__ __launch_bounds__(256) void k3_attn(
    const float* __restrict__ AW, const float* __restrict__ Ab, const float* __restrict__ cent)
{
    __shared__ float As[2][16][132];
    __shared__ float Bs[2][16][132];
    const int tid=threadIdx.x, bm=blockIdx.x*128, bn=blockIdx.y*128;
    ull acc[8][4];
    #pragma unroll
    for (int i=0;i<8;i++){ acc[i][0]=0; acc[i][1]=0; acc[i][2]=0; acc[i][3]=0; }
    const int rl=tid>>1, ks=(tid&1)*8;
    const float* arow = g_f + (size_t)(bm+rl)*D_ + ks;
    const float* wrow = AW + (size_t)(bn+rl)*D_ + ks;
    const int tm0=(tid>>4)*8, tn0=(tid&15)*8;
    float s3p = 0.f;
    float a8[8], w8[8];

    {   // preload tile 0
        float4 a0=*(const float4*)(arow);
        float4 a1=*(const float4*)(arow+4);
        float4 w0=*(const float4*)(wrow);
        float4 w1=*(const float4*)(wrow+4);
        a8[0]=a0.x;a8[1]=a0.y;a8[2]=a0.z;a8[3]=a0.w;a8[4]=a1.x;a8[5]=a1.y;a8[6]=a1.z;a8[7]=a1.w;
        w8[0]=w0.x;w8[1]=w0.y;w8[2]=w0.z;w8[3]=w0.w;w8[4]=w1.x;w8[5]=w1.y;w8[6]=w1.z;w8[7]=w1.w;
        #pragma unroll
        for (int i=0;i<8;i++){ As[0][ks+i][rl]=a8[i]; Bs[0][ks+i][rl]=w8[i]; s3p += a8[i]*a8[i]; }
    }
    __syncthreads();

    for (int kt=0; kt<16; kt++){
        const int cur = kt&1;
        if (kt < 15){
            const int k0 = (kt+1)*16;
            float4 a0=*(const float4*)(arow+k0);
            float4 a1=*(const float4*)(arow+k0+4);
            float4 w0=*(const float4*)(wrow+k0);
            float4 w1=*(const float4*)(wrow+k0+4);
            a8[0]=a0.x;a8[1]=a0.y;a8[2]=a0.z;a8[3]=a0.w;a8[4]=a1.x;a8[5]=a1.y;a8[6]=a1.z;a8[7]=a1.w;
            w8[0]=w0.x;w8[1]=w0.y;w8[2]=w0.z;w8[3]=w0.w;w8[4]=w1.x;w8[5]=w1.y;w8[6]=w1.z;w8[7]=w1.w;
        }
        gemm_tile(acc, As[cur], Bs[cur], tm0, tn0);
        if (kt < 15){
            #pragma unroll
            for (int i=0;i<8;i++){ As[cur^1][ks+i][rl]=a8[i]; Bs[cur^1][ks+i][rl]=w8[i]; s3p += a8[i]*a8[i]; }
        }
        __syncthreads();
    }

    // ||f||^2 per row (each element of row rl loaded exactly once by pair (tid, tid^1))
    if (blockIdx.y == 0){
        s3p += __shfl_xor_sync(0xffffffffu, s3p, 1);
        if ((tid&1)==0) g_s3[bm+rl] = s3p;
    }

    // epilogue: tanh + row partials (s1 = hyp.cent, s2 = ||hyp||^2) over this block's 128 cols
    float cenv[8], abv[8];
    #pragma unroll
    for (int j=0;j<8;j++){ cenv[j]=cent[bn+tn0+j]; abv[j]=Ab[bn+tn0+j]; }
    #pragma unroll
    for (int i=0;i<8;i++){
        float p1=0.f, p2=0.f;
        #pragma unroll
        for (int j=0;j<4;j++){
            float2 v=upk2(acc[i][j]);
            float h0 = ftanh(v.x + abv[2*j]);
            float h1 = ftanh(v.y + abv[2*j+1]);
            p1 += h0*cenv[2*j] + h1*cenv[2*j+1];
            p2 += h0*h0 + h1*h1;
        }
        #pragma unroll
        for (int off=8; off; off>>=1){
            p1 += __shfl_xor_sync(0xffffffffu, p1, off);
            p2 += __shfl_xor_sync(0xffffffffu, p2, off);
        }
        if ((tid&15)==0){
            g_s1p[(size_t)blockIdx.y*M_ + bm+tm0+i] = p1;
            g_s2p[(size_t)blockIdx.y*M_ + bm+tm0+i] = p2;
        }
    }
}

// ================= K4: per-row finalize: coef = exp(-beta*dist)*gamma, q = tanh(rf)/rf =======
__global__ __launch_bounds__(256) void k4_fin(const float* __restrict__ cent, const float* __restrict__ beta)
{
    __shared__ float swr[8];
    __shared__ float s_cu, s_suru, s_b;
    const int tid = threadIdx.x;
    { float c = cent[tid]; float v=c*c;
      #pragma unroll
      for (int o=16;o;o>>=1) v += __shfl_xor_sync(0xffffffffu, v, o);
      if ((tid&31)==0) swr[tid>>5]=v; }
    __syncthreads();
    if (tid==0){
        float s=0;
        #pragma unroll
        for (int i=0;i<8;i++) s+=swr[i];
        float ru = sqrtf(s);
        s_cu = coshf(ru); s_suru = sinhf(ru)/ru; s_b = beta[0];
    }
    __syncthreads();
    const size_t m = (size_t)blockIdx.x*256 + tid;
    float s1 = g_s1p[m] + g_s1p[M_+m];
    float s2 = g_s2p[m] + g_s2p[M_+m];
    float s3 = g_s3[m];
    float rr = sqrtf(s2);
    float x = coshf(rr)*s_cu - (sinhf(rr)/rr)*s_suru*s1;
    x = fminf(fmaxf(x, 1.f+1e-7f), 1e16f);
    float dist = logf(x) + log1pf(sqrtf(x*x - 1.f + 1e-7f)/x);
    float rf = sqrtf(s3);
    float th = tanhf(rf);
    float gsq = 1.f - th*th;
    gsq = fminf(fmaxf(gsq, 1e-7f), 1.f-1e-7f);
    float gam = 1.f/sqrtf(gsq);
    gam = fminf(fmaxf(gam, 1.f+1e-7f), 1e16f);
    g_coef[m] = expf(-s_b*dist)*gam;
    g_q[m] = th/rf;
}

// ================= K5: out[b][d] = sum_t coef*q*f / sum_t coef ===============================
__global__ __launch_bounds__(256) void k5_pool(float* __restrict__ out)
{
    __shared__ float cq[T_];
    __shared__ float sden;
    const int b = blockIdx.x, tid = threadIdx.x;
    if (tid < T_) cq[tid] = g_coef[tid*B_ + b];
    __syncthreads();
    if (tid==0){ float s=0; for (int t2=0;t2<T_;t2++) s+=cq[t2]; sden=s; }
    __syncthreads();
    if (tid < T_) cq[tid] = cq[tid]*g_q[tid*B_ + b]/sden;
    __syncthreads();
    float acc = 0.f;
    for (int t2=0;t2<T_;t2++)
        acc += cq[t2]*g_f[((size_t)t2*B_ + b)*D_ + tid];
    out[(size_t)b*D_ + tid] = acc;
}

extern "C" void kernel_launch(void* const* d_in, const int* in_sizes, int n_in,
                              void* d_out, int out_size)
{
    const int*   tok  = (const int*)d_in[0];
    const float* hid  = (const float*)d_in[1];
    const float* emb  = (const float*)d_in[2];
    const float* Wif  = (const float*)d_in[3];
    const float* Whf  = (const float*)d_in[4];
    const float* bif  = (const float*)d_in[5];
    const float* bhf  = (const float*)d_in[6];
    const float* Wib  = (const float*)d_in[7];
    const float* Whb  = (const float*)d_in[8];
    const float* bib  = (const float*)d_in[9];
    const float* bhb  = (const float*)d_in[10];
    const float* AW   = (const float*)d_in[11];
    const float* Ab   = (const float*)d_in[12];
    const float* cent = (const float*)d_in[13];
    const float* beta = (const float*)d_in[14];
    float* out = (float*)d_out;

    const int k2smem = 128*G3*4 + 128*8*4 + 128*12*8;
    cudaFuncSetAttribute(k2_gru, cudaFuncAttributeMaxDynamicSharedMemorySize, k2smem);

    k1_embed_proj<<<dim3(512,6),256>>>(tok, emb, Wif, Wib, bif, bib);
    k2_gru<<<dim3(64,2),256,k2smem>>>(hid, Whf, Whb, bhf, bhb, out + (size_t)B_*D_);
    k3_attn<<<dim3(512,2),256>>>(AW, Ab, cent);
    k4_fin<<<256,256>>>(cent, beta);
    k5_pool<<<512,256>>>(out);
}

// round 9
// speedup vs baseline: 1.6540x; 1.4153x over previous
#include <cuda_runtime.h>
#include <cuda_bf16.h>
#include <cstdint>

#define T_ 128
#define B_ 512
#define H_ 128
#define EMBD 300
#define D_ 256
#define G3 384
#define M_ (T_*B_)

__device__ float g_Pf[(size_t)M_*G3];
__device__ float g_Pb[(size_t)M_*G3];
__device__ float g_f[(size_t)M_*D_];
__device__ float g_s1p[2*M_];
__device__ float g_s2p[2*M_];
__device__ float g_s3[M_];
__device__ float g_coef[M_];
__device__ float g_q[M_];

typedef unsigned long long ull;
__device__ __forceinline__ void fma2(ull&c, ull a, ull b){ asm("fma.rn.f32x2 %0,%1,%2,%0;":"+l"(c):"l"(a),"l"(b)); }
__device__ __forceinline__ void add2(ull&c, ull a){ asm("add.rn.f32x2 %0,%0,%1;":"+l"(c):"l"(a)); }
__device__ __forceinline__ ull pk2(float lo,float hi){ ull r; asm("mov.b64 %0,{%1,%2};":"=l"(r):"f"(lo),"f"(hi)); return r; }
__device__ __forceinline__ float2 upk2(ull v){ float2 r; asm("mov.b64 {%0,%1},%2;":"=f"(r.x),"=f"(r.y):"l"(v)); return r; }
__device__ __forceinline__ float fsigm(float x){ return __fdividef(1.f, 1.f + __expf(-x)); }
__device__ __forceinline__ float ftanh(float x){ float e = __expf(2.f*x); return 1.f - __fdividef(2.f, e + 1.f); }

__device__ __forceinline__ unsigned smem_u32(const void* p){
    unsigned a; asm("{ .reg .u64 t; cvta.to.shared.u64 t, %1; cvt.u32.u64 %0, t; }":"=r"(a):"l"(p)); return a;
}
// pack two f32 -> bf16x2 (a in low half)
__device__ __forceinline__ unsigned bfp(float a, float b){ unsigned r; asm("cvt.rn.bf16x2.f32 %0,%1,%2;":"=r"(r):"f"(b),"f"(a)); return r; }
__device__ __forceinline__ unsigned lo_from(float a, float b, unsigned hp){
    float ha = __uint_as_float(hp << 16);
    float hb = __uint_as_float(hp & 0xffff0000u);
    return bfp(a - ha, b - hb);
}
__device__ __forceinline__ void sts128(unsigned addr, unsigned x, unsigned y, unsigned z, unsigned w){
    asm volatile("st.shared.v4.b32 [%0], {%1,%2,%3,%4};"::"r"(addr),"r"(x),"r"(y),"r"(z),"r"(w):"memory");
}
__device__ __forceinline__ void ldsm4(unsigned* r, unsigned addr){
    asm volatile("ldmatrix.sync.aligned.m8n8.x4.shared.b16 {%0,%1,%2,%3}, [%4];"
        : "=r"(r[0]),"=r"(r[1]),"=r"(r[2]),"=r"(r[3]) : "r"(addr));
}
__device__ __forceinline__ void mma16816(float* d, const unsigned* a, unsigned b0, unsigned b1){
    asm volatile("mma.sync.aligned.m16n8k16.row.col.f32.bf16.bf16.f32 "
        "{%0,%1,%2,%3}, {%4,%5,%6,%7}, {%8,%9}, {%0,%1,%2,%3};"
        : "+f"(d[0]),"+f"(d[1]),"+f"(d[2]),"+f"(d[3])
        : "r"(a[0]),"r"(a[1]),"r"(a[2]),"r"(a[3]), "r"(b0),"r"(b1));
}

// ================= K1: HMMA bf16-split GEMM =================
// C[65536,768] = emb[tok] @ W^T + bias. Block tile 128x128, 8 warps (4x2) of 32x64.
// Per 16-wide k-stage: smem holds Ahi/Alo/Bhi/Blo [128 rows][16 bf16, 48B stride].
// dyn smem: 2 stages x 24576 + toks(512) = 49664
#define K1_STG 24576u
#define K1_SMEM (2*24576 + 512)

__global__ __launch_bounds__(256) void k1_mma(
    const int* __restrict__ tok, const float* __restrict__ emb,
    const float* __restrict__ Wf, const float* __restrict__ Wb,
    const float* __restrict__ bf, const float* __restrict__ bb)
{
    extern __shared__ char smem[];
    const unsigned sb = smem_u32(smem);
    int* toks = (int*)(smem + 2*24576);
    const int tid = threadIdx.x;
    const int wid = tid >> 5, lane = tid & 31;
    const int bm = blockIdx.x*128, bn = blockIdx.y*128;
    if (tid < 128) toks[tid] = tok[bm + tid];
    __syncthreads();

    const int wm = wid >> 1, wn = wid & 1;          // warp 32x64 tile at (wm*32, wn*64)
    const int lrow = lane & 15;
    const unsigned lk = (lane >> 4) * 16;           // k-half byte offset for ldmatrix

    // loader: thread -> row r (0..127), k-half kh (0 or 8)
    const int r = tid >> 1, kh = (tid & 1) * 8;
    const float* arow = emb + (size_t)toks[r]*EMBD;
    const int ng = bn + r;
    const float* wrow = (ng < G3) ? (Wf + (size_t)ng*EMBD) : (Wb + (size_t)(ng-G3)*EMBD);
    const unsigned soff = (unsigned)(r*48 + kh*2);

    float acc[2][8][4];
    #pragma unroll
    for (int i=0;i<2;i++)
        #pragma unroll
        for (int j=0;j<8;j++)
            #pragma unroll
            for (int q=0;q<4;q++) acc[i][j][q]=0.f;

    // prologue: load+convert stage 0
    float4 av0,av1,bv0,bv1;
    {
        const int col = kh;
        av0 = *(const float4*)(arow+col); av1 = *(const float4*)(arow+col+4);
        bv0 = *(const float4*)(wrow+col); bv1 = *(const float4*)(wrow+col+4);
        unsigned ah0=bfp(av0.x,av0.y), ah1=bfp(av0.z,av0.w), ah2=bfp(av1.x,av1.y), ah3=bfp(av1.z,av1.w);
        unsigned bh0=bfp(bv0.x,bv0.y), bh1=bfp(bv0.z,bv0.w), bh2=bfp(bv1.x,bv1.y), bh3=bfp(bv1.z,bv1.w);
        sts128(sb + soff,          ah0,ah1,ah2,ah3);
        sts128(sb + 6144u + soff,  lo_from(av0.x,av0.y,ah0), lo_from(av0.z,av0.w,ah1), lo_from(av1.x,av1.y,ah2), lo_from(av1.z,av1.w,ah3));
        sts128(sb + 12288u + soff, bh0,bh1,bh2,bh3);
        sts128(sb + 18432u + soff, lo_from(bv0.x,bv0.y,bh0), lo_from(bv0.z,bv0.w,bh1), lo_from(bv1.x,bv1.y,bh2), lo_from(bv1.z,bv1.w,bh3));
    }
    __syncthreads();

    for (int kt=0; kt<19; kt++){
        const unsigned base = sb + (unsigned)(kt & 1)*K1_STG;
        const unsigned nbase = sb + (unsigned)((kt & 1)^1)*K1_STG;
        // issue next-stage global loads first (long-scoreboard overlap with MMA)
        if (kt < 18){
            const int col = (kt+1)*16 + kh;
            const float4 z4 = make_float4(0.f,0.f,0.f,0.f);
            av0 = (col   < EMBD) ? *(const float4*)(arow+col)   : z4;
            av1 = (col+4 < EMBD) ? *(const float4*)(arow+col+4) : z4;
            bv0 = (col   < EMBD) ? *(const float4*)(wrow+col)   : z4;
            bv1 = (col+4 < EMBD) ? *(const float4*)(wrow+col+4) : z4;
        }
        // fragments
        unsigned ahi[2][4], alo[2][4];
        #pragma unroll
        for (int mi=0; mi<2; mi++){
            unsigned ad = base + (unsigned)((wm*32 + mi*16 + lrow)*48) + lk;
            ldsm4(ahi[mi], ad);
            ldsm4(alo[mi], ad + 6144u);
        }
        #pragma unroll
        for (int np=0; np<4; np++){
            unsigned bd = base + 12288u + (unsigned)((wn*64 + np*16 + lrow)*48) + lk;
            unsigned bh[4], bl[4];
            ldsm4(bh, bd);
            ldsm4(bl, bd + 6144u);
            #pragma unroll
            for (int mi=0; mi<2; mi++){
                mma16816(acc[mi][2*np],   ahi[mi], bh[0], bh[2]);
                mma16816(acc[mi][2*np+1], ahi[mi], bh[1], bh[3]);
                mma16816(acc[mi][2*np],   alo[mi], bh[0], bh[2]);
                mma16816(acc[mi][2*np+1], alo[mi], bh[1], bh[3]);
                mma16816(acc[mi][2*np],   ahi[mi], bl[0], bl[2]);
                mma16816(acc[mi][2*np+1], ahi[mi], bl[1], bl[3]);
            }
        }
        // convert+store next stage
        if (kt < 18){
            unsigned ah0=bfp(av0.x,av0.y), ah1=bfp(av0.z,av0.w), ah2=bfp(av1.x,av1.y), ah3=bfp(av1.z,av1.w);
            unsigned bh0=bfp(bv0.x,bv0.y), bh1=bfp(bv0.z,bv0.w), bh2=bfp(bv1.x,bv1.y), bh3=bfp(bv1.z,bv1.w);
            sts128(nbase + soff,          ah0,ah1,ah2,ah3);
            sts128(nbase + 6144u + soff,  lo_from(av0.x,av0.y,ah0), lo_from(av0.z,av0.w,ah1), lo_from(av1.x,av1.y,ah2), lo_from(av1.z,av1.w,ah3));
            sts128(nbase + 12288u + soff, bh0,bh1,bh2,bh3);
            sts128(nbase + 18432u + soff, lo_from(bv0.x,bv0.y,bh0), lo_from(bv0.z,bv0.w,bh1), lo_from(bv1.x,bv1.y,bh2), lo_from(bv1.z,bv1.w,bh3));
        }
        __syncthreads();
    }

    // epilogue: direct fragment stores + bias
    float* dst; const float* bias_; int nb;
    if (bn < G3){ dst = g_Pf; nb = bn; bias_ = bf; } else { dst = g_Pb; nb = bn - G3; bias_ = bb; }
    const int g = lane >> 2, tg = (lane & 3)*2;
    #pragma unroll
    for (int mi=0; mi<2; mi++){
        const int row = bm + wm*32 + mi*16 + g;
        #pragma unroll
        for (int ni=0; ni<8; ni++){
            const int c = wn*64 + ni*8 + tg;
            const float b0 = bias_[nb + c], b1 = bias_[nb + c + 1];
            float2 v0 = make_float2(acc[mi][ni][0] + b0, acc[mi][ni][1] + b1);
            float2 v1 = make_float2(acc[mi][ni][2] + b0, acc[mi][ni][3] + b1);
            *(float2*)(dst + (size_t)row*G3 + nb + c) = v0;
            *(float2*)(dst + (size_t)(row+8)*G3 + nb + c) = v1;
        }
    }
}

// ================= K2: bidirectional GRU, grid(64,2), 256 threads (2 k-slices) =================
__global__ __launch_bounds__(256) void k2_gru(
    const float* __restrict__ hidden,
    const float* __restrict__ Whf, const float* __restrict__ Whb,
    const float* __restrict__ bhf, const float* __restrict__ bhb,
    float* __restrict__ outH)
{
    extern __shared__ float sm[];
    float* ws = sm;
    float* hs = sm + 128*G3;
    ull*   pbuf = (ull*)(sm + 128*G3 + 128*8);

    const int dir = blockIdx.y, b0 = blockIdx.x*8;
    const int tid = threadIdx.x;
    const int t = tid & 127;
    const int half = tid >> 7;
    const int kbase = half * 64;
    const float* W  = dir? Whb : Whf;
    const float* bh = dir? bhb : bhf;
    const float* P  = dir? g_Pb : g_Pf;

    for (int idx = tid; idx < 128*G3; idx += 256){
        int j = idx >> 7, k = idx & 127;
        ws[k*G3 + j] = W[(size_t)j*H_ + k];
    }
    float hreg[8];
    if (half == 0){
        #pragma unroll
        for (int bi=0;bi<8;bi++){
            float hv = hidden[(size_t)dir*B_*H_ + (size_t)(b0+bi)*H_ + t];
            hreg[bi]=hv; hs[t*8+bi]=hv;
        }
    }
    const float br=bh[t], bz=bh[H_+t], bn2=bh[2*H_+t];
    __syncthreads();
    const ull* h64 = (const ull*)hs;

    for (int s=0;s<T_;s++){
        const int tt = dir ? (T_-1-s) : s;
        float xr[8],xz[8],xn[8];
        if (half == 0){
            const float* prow = P + ((size_t)tt*B_ + b0)*G3;
            #pragma unroll
            for (int bi=0;bi<8;bi++){
                xr[bi]=prow[bi*G3+t]; xz[bi]=prow[bi*G3+H_+t]; xn[bi]=prow[bi*G3+2*H_+t];
            }
        }
        ull ar[4],az[4],an[4];
        if (half == 0){
            ull pr=pk2(br,br), pz=pk2(bz,bz), pn=pk2(bn2,bn2);
            #pragma unroll
            for (int p=0;p<4;p++){ ar[p]=pr; az[p]=pz; an[p]=pn; }
        } else {
            #pragma unroll
            for (int p=0;p<4;p++){ ar[p]=0; az[p]=0; an[p]=0; }
        }
        #pragma unroll 4
        for (int k=kbase; k<kbase+64; k++){
            const float* wk = ws + k*G3 + t;
            float w0=wk[0], w1=wk[H_], w2=wk[2*H_];
            ull p0=pk2(w0,w0), p1=pk2(w1,w1), p2=pk2(w2,w2);
            #pragma unroll
            for (int p=0;p<4;p++){
                ull hp = h64[k*4+p];
                fma2(ar[p],hp,p0); fma2(az[p],hp,p1); fma2(an[p],hp,p2);
            }
        }
        if (half == 1){
            #pragma unroll
            for (int p=0;p<4;p++){ pbuf[t*12+p]=ar[p]; pbuf[t*12+4+p]=az[p]; pbuf[t*12+8+p]=an[p]; }
        }
        __syncthreads();
        if (half == 0){
            #pragma unroll
            for (int p=0;p<4;p++){ add2(ar[p],pbuf[t*12+p]); add2(az[p],pbuf[t*12+4+p]); add2(an[p],pbuf[t*12+8+p]); }
            #pragma unroll
            for (int p=0;p<4;p++){
                float2 gr=upk2(ar[p]), gz=upk2(az[p]), gn=upk2(an[p]);
                #pragma unroll
                for (int l=0;l<2;l++){
                    int bi = 2*p+l;
                    float r = fsigm(xr[bi] + (l?gr.y:gr.x));
                    float z = fsigm(xz[bi] + (l?gz.y:gz.x));
                    float n = ftanh(xn[bi] + r*(l?gn.y:gn.x));
                    float h2 = (1.f-z)*n + z*hreg[bi];
                    hreg[bi]=h2; hs[t*8+bi]=h2;
                    g_f[((size_t)tt*B_ + (b0+bi))*D_ + dir*H_ + t] = h2;
                }
            }
        }
        __syncthreads();
    }
    if (half == 0){
        #pragma unroll
        for (int bi=0;bi<8;bi++)
            outH[(size_t)dir*B_*H_ + (size_t)(b0+bi)*H_ + t] = hreg[bi];
    }
}

// shared 128x128x16 tile compute, 8x8 microtile, FFMA2 (K3)
__device__ __forceinline__ void gemm_tile(ull acc[8][4], const float (*As)[132], const float (*Bs)[132], int tm0, int tn0)
{
    #pragma unroll
    for (int k=0;k<16;k++){
        float4 a0=*(const float4*)&As[k][tm0];
        float4 a1=*(const float4*)&As[k][tm0+4];
        float4 b0=*(const float4*)&Bs[k][tn0];
        float4 b1=*(const float4*)&Bs[k][tn0+4];
        ull bp0=pk2(b0.x,b0.y), bp1=pk2(b0.z,b0.w), bp2=pk2(b1.x,b1.y), bp3=pk2(b1.z,b1.w);
        float av[8] = { a0.x,a0.y,a0.z,a0.w,a1.x,a1.y,a1.z,a1.w };
        #pragma unroll
        for (int i=0;i<8;i++){
            ull ad=pk2(av[i],av[i]);
            fma2(acc[i][0],ad,bp0); fma2(acc[i][1],ad,bp1);
            fma2(acc[i][2],ad,bp2); fma2(acc[i][3],ad,bp3);
        }
    }
}

// ============ K3: hyp=tanh(f@AW^T+Ab) fused with per-row reductions (no hyp store) ============
__global__ __launch_bounds__(256) void k3_attn(
    const float* __restrict__ AW, const float* __restrict__ Ab, const float* __restrict__ cent)
{
    __shared__ float As[2][16][132];
    __shared__ float Bs[2][16][132];
    const int tid=threadIdx.x, bm=blockIdx.x*128, bn=blockIdx.y*128;
    ull acc[8][4];
    #pragma unroll
    for (int i=0;i<8;i++){ acc[i][0]=0; acc[i][1]=0; acc[i][2]=0; acc[i][3]=0; }
    const int rl=tid>>1, ks=(tid&1)*8;
    const float* arow = g_f + (size_t)(bm+rl)*D_ + ks;
    const float* wrow = AW + (size_t)(bn+rl)*D_ + ks;
    const int tm0=(tid>>4)*8, tn0=(tid&15)*8;
    float s3p = 0.f;
    float a8[8], w8[8];

    {
        float4 a0=*(const float4*)(arow);
        float4 a1=*(const float4*)(arow+4);
        float4 w0=*(const float4*)(wrow);
        float4 w1=*(const float4*)(wrow+4);
        a8[0]=a0.x;a8[1]=a0.y;a8[2]=a0.z;a8[3]=a0.w;a8[4]=a1.x;a8[5]=a1.y;a8[6]=a1.z;a8[7]=a1.w;
        w8[0]=w0.x;w8[1]=w0.y;w8[2]=w0.z;w8[3]=w0.w;w8[4]=w1.x;w8[5]=w1.y;w8[6]=w1.z;w8[7]=w1.w;
        #pragma unroll
        for (int i=0;i<8;i++){ As[0][ks+i][rl]=a8[i]; Bs[0][ks+i][rl]=w8[i]; s3p += a8[i]*a8[i]; }
    }
    __syncthreads();

    for (int kt=0; kt<16; kt++){
        const int cur = kt&1;
        if (kt < 15){
            const int k0 = (kt+1)*16;
            float4 a0=*(const float4*)(arow+k0);
            float4 a1=*(const float4*)(arow+k0+4);
            float4 w0=*(const float4*)(wrow+k0);
            float4 w1=*(const float4*)(wrow+k0+4);
            a8[0]=a0.x;a8[1]=a0.y;a8[2]=a0.z;a8[3]=a0.w;a8[4]=a1.x;a8[5]=a1.y;a8[6]=a1.z;a8[7]=a1.w;
            w8[0]=w0.x;w8[1]=w0.y;w8[2]=w0.z;w8[3]=w0.w;w8[4]=w1.x;w8[5]=w1.y;w8[6]=w1.z;w8[7]=w1.w;
        }
        gemm_tile(acc, As[cur], Bs[cur], tm0, tn0);
        if (kt < 15){
            #pragma unroll
            for (int i=0;i<8;i++){ As[cur^1][ks+i][rl]=a8[i]; Bs[cur^1][ks+i][rl]=w8[i]; s3p += a8[i]*a8[i]; }
        }
        __syncthreads();
    }

    if (blockIdx.y == 0){
        s3p += __shfl_xor_sync(0xffffffffu, s3p, 1);
        if ((tid&1)==0) g_s3[bm+rl] = s3p;
    }

    float cenv[8], abv[8];
    #pragma unroll
    for (int j=0;j<8;j++){ cenv[j]=cent[bn+tn0+j]; abv[j]=Ab[bn+tn0+j]; }
    #pragma unroll
    for (int i=0;i<8;i++){
        float p1=0.f, p2=0.f;
        #pragma unroll
        for (int j=0;j<4;j++){
            float2 v=upk2(acc[i][j]);
            float h0 = ftanh(v.x + abv[2*j]);
            float h1 = ftanh(v.y + abv[2*j+1]);
            p1 += h0*cenv[2*j] + h1*cenv[2*j+1];
            p2 += h0*h0 + h1*h1;
        }
        #pragma unroll
        for (int off=8; off; off>>=1){
            p1 += __shfl_xor_sync(0xffffffffu, p1, off);
            p2 += __shfl_xor_sync(0xffffffffu, p2, off);
        }
        if ((tid&15)==0){
            g_s1p[(size_t)blockIdx.y*M_ + bm+tm0+i] = p1;
            g_s2p[(size_t)blockIdx.y*M_ + bm+tm0+i] = p2;
        }
    }
}

// ================= K4: per-row finalize =================
__global__ __launch_bounds__(256) void k4_fin(const float* __restrict__ cent, const float* __restrict__ beta)
{
    __shared__ float swr[8];
    __shared__ float s_cu, s_suru, s_b;
    const int tid = threadIdx.x;
    { float c = cent[tid]; float v=c*c;
      #pragma unroll
      for (int o=16;o;o>>=1) v += __shfl_xor_sync(0xffffffffu, v, o);
      if ((tid&31)==0) swr[tid>>5]=v; }
    __syncthreads();
    if (tid==0){
        float s=0;
        #pragma unroll
        for (int i=0;i<8;i++) s+=swr[i];
        float ru = sqrtf(s);
        s_cu = coshf(ru); s_suru = sinhf(ru)/ru; s_b = beta[0];
    }
    __syncthreads();
    const size_t m = (size_t)blockIdx.x*256 + tid;
    float s1 = g_s1p[m] + g_s1p[M_+m];
    float s2 = g_s2p[m] + g_s2p[M_+m];
    float s3 = g_s3[m];
    float rr = sqrtf(s2);
    float x = coshf(rr)*s_cu - (sinhf(rr)/rr)*s_suru*s1;
    x = fminf(fmaxf(x, 1.f+1e-7f), 1e16f);
    float dist = logf(x) + log1pf(sqrtf(x*x - 1.f + 1e-7f)/x);
    float rf = sqrtf(s3);
    float th = tanhf(rf);
    float gsq = 1.f - th*th;
    gsq = fminf(fmaxf(gsq, 1e-7f), 1.f-1e-7f);
    float gam = 1.f/sqrtf(gsq);
    gam = fminf(fmaxf(gam, 1.f+1e-7f), 1e16f);
    g_coef[m] = expf(-s_b*dist)*gam;
    g_q[m] = th/rf;
}

// ================= K5: pooling =================
__global__ __launch_bounds__(256) void k5_pool(float* __restrict__ out)
{
    __shared__ float cq[T_];
    __shared__ float sden;
    const int b = blockIdx.x, tid = threadIdx.x;
    if (tid < T_) cq[tid] = g_coef[tid*B_ + b];
    __syncthreads();
    if (tid==0){ float s=0; for (int t2=0;t2<T_;t2++) s+=cq[t2]; sden=s; }
    __syncthreads();
    if (tid < T_) cq[tid] = cq[tid]*g_q[tid*B_ + b]/sden;
    __syncthreads();
    float acc = 0.f;
    for (int t2=0;t2<T_;t2++)
        acc += cq[t2]*g_f[((size_t)t2*B_ + b)*D_ + tid];
    out[(size_t)b*D_ + tid] = acc;
}

extern "C" void kernel_launch(void* const* d_in, const int* in_sizes, int n_in,
                              void* d_out, int out_size)
{
    const int*   tok  = (const int*)d_in[0];
    const float* hid  = (const float*)d_in[1];
    const float* emb  = (const float*)d_in[2];
    const float* Wif  = (const float*)d_in[3];
    const float* Whf  = (const float*)d_in[4];
    const float* bif  = (const float*)d_in[5];
    const float* bhf  = (const float*)d_in[6];
    const float* Wib  = (const float*)d_in[7];
    const float* Whb  = (const float*)d_in[8];
    const float* bib  = (const float*)d_in[9];
    const float* bhb  = (const float*)d_in[10];
    const float* AW   = (const float*)d_in[11];
    const float* Ab   = (const float*)d_in[12];
    const float* cent = (const float*)d_in[13];
    const float* beta = (const float*)d_in[14];
    float* out = (float*)d_out;

    cudaFuncSetAttribute(k1_mma, cudaFuncAttributeMaxDynamicSharedMemorySize, K1_SMEM);
    const int k2smem = 128*G3*4 + 128*8*4 + 128*12*8;
    cudaFuncSetAttribute(k2_gru, cudaFuncAttributeMaxDynamicSharedMemorySize, k2smem);

    k1_mma<<<dim3(512,6),256,K1_SMEM>>>(tok, emb, Wif, Wib, bif, bib);
    k2_gru<<<dim3(64,2),256,k2smem>>>(hid, Whf, Whb, bhf, bhb, out + (size_t)B_*D_);
    k3_attn<<<dim3(512,2),256>>>(AW, Ab, cent);
    k4_fin<<<256,256>>>(cent, beta);
    k5_pool<<<512,256>>>(out);
}

// round 10
// speedup vs baseline: 1.6903x; 1.0219x over previous
#include <cuda_runtime.h>
#include <cuda_bf16.h>
#include <cstdint>

#define T_ 128
#define B_ 512
#define H_ 128
#define EMBD 300
#define D_ 256
#define G3 384
#define M_ (T_*B_)

__device__ float g_Pf[(size_t)M_*G3];
__device__ float g_Pb[(size_t)M_*G3];
__device__ float g_f[(size_t)M_*D_];
__device__ float g_s1p[2*M_];
__device__ float g_s2p[2*M_];
__device__ float g_s3[M_];
__device__ float g_coef[M_];
__device__ float g_q[M_];

typedef unsigned long long ull;
__device__ __forceinline__ void fma2(ull&c, ull a, ull b){ asm("fma.rn.f32x2 %0,%1,%2,%0;":"+l"(c):"l"(a),"l"(b)); }
__device__ __forceinline__ void add2(ull&c, ull a){ asm("add.rn.f32x2 %0,%0,%1;":"+l"(c):"l"(a)); }
__device__ __forceinline__ ull pk2(float lo,float hi){ ull r; asm("mov.b64 %0,{%1,%2};":"=l"(r):"f"(lo),"f"(hi)); return r; }
__device__ __forceinline__ float2 upk2(ull v){ float2 r; asm("mov.b64 {%0,%1},%2;":"=f"(r.x),"=f"(r.y):"l"(v)); return r; }
__device__ __forceinline__ float fsigm(float x){ return __fdividef(1.f, 1.f + __expf(-x)); }
__device__ __forceinline__ float ftanh(float x){ float e = __expf(2.f*x); return 1.f - __fdividef(2.f, e + 1.f); }

__device__ __forceinline__ unsigned smem_u32(const void* p){
    unsigned a; asm("{ .reg .u64 t; cvta.to.shared.u64 t, %1; cvt.u32.u64 %0, t; }":"=r"(a):"l"(p)); return a;
}
__device__ __forceinline__ unsigned bfp(float a, float b){ unsigned r; asm("cvt.rn.bf16x2.f32 %0,%1,%2;":"=r"(r):"f"(b),"f"(a)); return r; }
__device__ __forceinline__ unsigned lo_from(float a, float b, unsigned hp){
    float ha = __uint_as_float(hp << 16);
    float hb = __uint_as_float(hp & 0xffff0000u);
    return bfp(a - ha, b - hb);
}
__device__ __forceinline__ void sts128(unsigned addr, unsigned x, unsigned y, unsigned z, unsigned w){
    asm volatile("st.shared.v4.b32 [%0], {%1,%2,%3,%4};"::"r"(addr),"r"(x),"r"(y),"r"(z),"r"(w):"memory");
}
__device__ __forceinline__ void ldsm4(unsigned* r, unsigned addr){
    asm volatile("ldmatrix.sync.aligned.m8n8.x4.shared.b16 {%0,%1,%2,%3}, [%4];"
        : "=r"(r[0]),"=r"(r[1]),"=r"(r[2]),"=r"(r[3]) : "r"(addr));
}
__device__ __forceinline__ void mma16816(float* d, const unsigned* a, unsigned b0, unsigned b1){
    asm volatile("mma.sync.aligned.m16n8k16.row.col.f32.bf16.bf16.f32 "
        "{%0,%1,%2,%3}, {%4,%5,%6,%7}, {%8,%9}, {%0,%1,%2,%3};"
        : "+f"(d[0]),"+f"(d[1]),"+f"(d[2]),"+f"(d[3])
        : "r"(a[0]),"r"(a[1]),"r"(a[2]),"r"(a[3]), "r"(b0),"r"(b1));
}

// ================= K1: HMMA bf16-split GEMM (unchanged, passing) =================
#define K1_STG 24576u
#define K1_SMEM (2*24576 + 512)

__global__ __launch_bounds__(256) void k1_mma(
    const int* __restrict__ tok, const float* __restrict__ emb,
    const float* __restrict__ Wf, const float* __restrict__ Wb,
    const float* __restrict__ bf, const float* __restrict__ bb)
{
    extern __shared__ char smem[];
    const unsigned sb = smem_u32(smem);
    int* toks = (int*)(smem + 2*24576);
    const int tid = threadIdx.x;
    const int wid = tid >> 5, lane = tid & 31;
    const int bm = blockIdx.x*128, bn = blockIdx.y*128;
    if (tid < 128) toks[tid] = tok[bm + tid];
    __syncthreads();

    const int wm = wid >> 1, wn = wid & 1;
    const int lrow = lane & 15;
    const unsigned lk = (lane >> 4) * 16;
    const int r = tid >> 1, kh = (tid & 1) * 8;
    const float* arow = emb + (size_t)toks[r]*EMBD;
    const int ng = bn + r;
    const float* wrow = (ng < G3) ? (Wf + (size_t)ng*EMBD) : (Wb + (size_t)(ng-G3)*EMBD);
    const unsigned soff = (unsigned)(r*48 + kh*2);

    float acc[2][8][4];
    #pragma unroll
    for (int i=0;i<2;i++)
        #pragma unroll
        for (int j=0;j<8;j++)
            #pragma unroll
            for (int q=0;q<4;q++) acc[i][j][q]=0.f;

    float4 av0,av1,bv0,bv1;
    {
        av0 = *(const float4*)(arow+kh); av1 = *(const float4*)(arow+kh+4);
        bv0 = *(const float4*)(wrow+kh); bv1 = *(const float4*)(wrow+kh+4);
        unsigned ah0=bfp(av0.x,av0.y), ah1=bfp(av0.z,av0.w), ah2=bfp(av1.x,av1.y), ah3=bfp(av1.z,av1.w);
        unsigned bh0=bfp(bv0.x,bv0.y), bh1=bfp(bv0.z,bv0.w), bh2=bfp(bv1.x,bv1.y), bh3=bfp(bv1.z,bv1.w);
        sts128(sb + soff,          ah0,ah1,ah2,ah3);
        sts128(sb + 6144u + soff,  lo_from(av0.x,av0.y,ah0), lo_from(av0.z,av0.w,ah1), lo_from(av1.x,av1.y,ah2), lo_from(av1.z,av1.w,ah3));
        sts128(sb + 12288u + soff, bh0,bh1,bh2,bh3);
        sts128(sb + 18432u + soff, lo_from(bv0.x,bv0.y,bh0), lo_from(bv0.z,bv0.w,bh1), lo_from(bv1.x,bv1.y,bh2), lo_from(bv1.z,bv1.w,bh3));
    }
    __syncthreads();

    for (int kt=0; kt<19; kt++){
        const unsigned base = sb + (unsigned)(kt & 1)*K1_STG;
        const unsigned nbase = sb + (unsigned)((kt & 1)^1)*K1_STG;
        if (kt < 18){
            const int col = (kt+1)*16 + kh;
            const float4 z4 = make_float4(0.f,0.f,0.f,0.f);
            av0 = (col   < EMBD) ? *(const float4*)(arow+col)   : z4;
            av1 = (col+4 < EMBD) ? *(const float4*)(arow+col+4) : z4;
            bv0 = (col   < EMBD) ? *(const float4*)(wrow+col)   : z4;
            bv1 = (col+4 < EMBD) ? *(const float4*)(wrow+col+4) : z4;
        }
        unsigned ahi[2][4], alo[2][4];
        #pragma unroll
        for (int mi=0; mi<2; mi++){
            unsigned ad = base + (unsigned)((wm*32 + mi*16 + lrow)*48) + lk;
            ldsm4(ahi[mi], ad);
            ldsm4(alo[mi], ad + 6144u);
        }
        #pragma unroll
        for (int np=0; np<4; np++){
            unsigned bd = base + 12288u + (unsigned)((wn*64 + np*16 + lrow)*48) + lk;
            unsigned bh[4], bl[4];
            ldsm4(bh, bd);
            ldsm4(bl, bd + 6144u);
            #pragma unroll
            for (int mi=0; mi<2; mi++){
                mma16816(acc[mi][2*np],   ahi[mi], bh[0], bh[2]);
                mma16816(acc[mi][2*np+1], ahi[mi], bh[1], bh[3]);
                mma16816(acc[mi][2*np],   alo[mi], bh[0], bh[2]);
                mma16816(acc[mi][2*np+1], alo[mi], bh[1], bh[3]);
                mma16816(acc[mi][2*np],   ahi[mi], bl[0], bl[2]);
                mma16816(acc[mi][2*np+1], ahi[mi], bl[1], bl[3]);
            }
        }
        if (kt < 18){
            unsigned ah0=bfp(av0.x,av0.y), ah1=bfp(av0.z,av0.w), ah2=bfp(av1.x,av1.y), ah3=bfp(av1.z,av1.w);
            unsigned bh0=bfp(bv0.x,bv0.y), bh1=bfp(bv0.z,bv0.w), bh2=bfp(bv1.x,bv1.y), bh3=bfp(bv1.z,bv1.w);
            sts128(nbase + soff,          ah0,ah1,ah2,ah3);
            sts128(nbase + 6144u + soff,  lo_from(av0.x,av0.y,ah0), lo_from(av0.z,av0.w,ah1), lo_from(av1.x,av1.y,ah2), lo_from(av1.z,av1.w,ah3));
            sts128(nbase + 12288u + soff, bh0,bh1,bh2,bh3);
            sts128(nbase + 18432u + soff, lo_from(bv0.x,bv0.y,bh0), lo_from(bv0.z,bv0.w,bh1), lo_from(bv1.x,bv1.y,bh2), lo_from(bv1.z,bv1.w,bh3));
        }
        __syncthreads();
    }

    float* dst; const float* bias_; int nb;
    if (bn < G3){ dst = g_Pf; nb = bn; bias_ = bf; } else { dst = g_Pb; nb = bn - G3; bias_ = bb; }
    const int g = lane >> 2, tg = (lane & 3)*2;
    #pragma unroll
    for (int mi=0; mi<2; mi++){
        const int row = bm + wm*32 + mi*16 + g;
        #pragma unroll
        for (int ni=0; ni<8; ni++){
            const int c = wn*64 + ni*8 + tg;
            const float b0 = bias_[nb + c], b1 = bias_[nb + c + 1];
            float2 v0 = make_float2(acc[mi][ni][0] + b0, acc[mi][ni][1] + b1);
            float2 v1 = make_float2(acc[mi][ni][2] + b0, acc[mi][ni][3] + b1);
            *(float2*)(dst + (size_t)row*G3 + nb + c) = v0;
            *(float2*)(dst + (size_t)(row+8)*G3 + nb + c) = v1;
        }
    }
}

// ================= K2: GRU, grid(64,2), 256 threads, symmetric k/batch split =================
// smem floats: wrz[k][t] float2 @0 (32768), wn[k][t] @32768 (16384), hs @49152 (1024),
//              pbuf (ull[128][2][6]) @50176 (3072). Total 53248 floats = 212992 B.
#define K2_SMEM 212992

__global__ __launch_bounds__(256) void k2_gru(
    const float* __restrict__ hidden,
    const float* __restrict__ Whf, const float* __restrict__ Whb,
    const float* __restrict__ bhf, const float* __restrict__ bhb,
    float* __restrict__ outH)
{
    extern __shared__ float sm[];
    float2* wrz = (float2*)sm;
    float*  wn  = sm + 32768;
    float*  hs  = sm + 49152;
    ull*    pbuf= (ull*)(sm + 50176);

    const int dir = blockIdx.y, b0 = blockIdx.x*8;
    const int tid = threadIdx.x;
    const int t = tid & 127;
    const int half = tid >> 7;
    const int kbase = half * 64;
    const float* W  = dir? Whb : Whf;
    const float* bh = dir? bhb : bhf;
    const float* P  = dir? g_Pb : g_Pf;

    for (int idx = tid; idx < 128*G3; idx += 256){
        int j = idx >> 7, k = idx & 127;
        float w = W[(size_t)j*H_ + k];
        if (j < 128)      ((float*)wrz)[(k*128 + j)*2]       = w;
        else if (j < 256) ((float*)wrz)[(k*128 + (j-128))*2+1] = w;
        else              wn[k*128 + (j-256)] = w;
    }
    float hreg[4];
    #pragma unroll
    for (int j=0;j<4;j++){
        int bi = half*4 + j;
        float hv = hidden[(size_t)dir*B_*H_ + (size_t)(b0+bi)*H_ + t];
        hreg[j]=hv; hs[t*8+bi]=hv;
    }
    const float br=bh[t], bz=bh[H_+t], bn2=bh[2*H_+t];
    __syncthreads();
    const longlong2* h128 = (const longlong2*)hs;
    const int po = 2 - 2*half;   // pairs exported
    const int pkp = 2*half;      // pairs kept

    for (int s=0;s<T_;s++){
        const int tt = dir ? (T_-1-s) : s;
        const float* prow = P + ((size_t)tt*B_ + b0)*G3;
        float xr[4],xz[4],xn[4];
        #pragma unroll
        for (int j=0;j<4;j++){
            int bi = half*4 + j;
            xr[j]=prow[bi*G3+t]; xz[j]=prow[bi*G3+H_+t]; xn[j]=prow[bi*G3+2*H_+t];
        }
        ull ar[4],az[4],an[4];
        #pragma unroll
        for (int p=0;p<4;p++){ ar[p]=0; az[p]=0; an[p]=0; }
        #pragma unroll 4
        for (int k=kbase; k<kbase+64; k++){
            float2 wv = wrz[k*128+t];
            float wnv = wn[k*128+t];
            ull p0=pk2(wv.x,wv.x), p1=pk2(wv.y,wv.y), p2=pk2(wnv,wnv);
            longlong2 hA = h128[k*2], hB = h128[k*2+1];
            ull h0=(ull)hA.x, h1=(ull)hA.y, h2=(ull)hB.x, h3=(ull)hB.y;
            fma2(ar[0],h0,p0); fma2(ar[1],h1,p0); fma2(ar[2],h2,p0); fma2(ar[3],h3,p0);
            fma2(az[0],h0,p1); fma2(az[1],h1,p1); fma2(az[2],h2,p1); fma2(az[3],h3,p1);
            fma2(an[0],h0,p2); fma2(an[1],h1,p2); fma2(an[2],h2,p2); fma2(an[3],h3,p2);
        }
        {
            ull* ms = pbuf + (t*2 + half)*6;
            ms[0]=ar[po]; ms[1]=ar[po+1]; ms[2]=az[po]; ms[3]=az[po+1]; ms[4]=an[po]; ms[5]=an[po+1];
        }
        __syncthreads();
        {
            const ull* os = pbuf + (t*2 + (half^1))*6;
            add2(ar[pkp],os[0]); add2(ar[pkp+1],os[1]);
            add2(az[pkp],os[2]); add2(az[pkp+1],os[3]);
            add2(an[pkp],os[4]); add2(an[pkp+1],os[5]);
        }
        #pragma unroll
        for (int j=0;j<4;j++){
            int bi = half*4 + j;
            int p = pkp + (j>>1);
            float2 gr=upk2(ar[p]), gz=upk2(az[p]), gn=upk2(an[p]);
            float grv=(j&1)?gr.y:gr.x, gzv=(j&1)?gz.y:gz.x, gnv=(j&1)?gn.y:gn.x;
            float rg = fsigm(xr[j] + grv + br);
            float zg = fsigm(xz[j] + gzv + bz);
            float ng = ftanh(xn[j] + rg*(gnv + bn2));
            float h2 = (1.f-zg)*ng + zg*hreg[j];
            hreg[j]=h2; hs[t*8+bi]=h2;
            g_f[((size_t)tt*B_ + (b0+bi))*D_ + dir*H_ + t] = h2;
        }
        __syncthreads();
    }
    #pragma unroll
    for (int j=0;j<4;j++){
        int bi = half*4 + j;
        outH[(size_t)dir*B_*H_ + (size_t)(b0+bi)*H_ + t] = hreg[j];
    }
}

// ============ K3: HMMA bf16-split, tanh epilogue fused with row reductions ============
#define K3_SMEM (2*24576 + 2048)

__global__ __launch_bounds__(256) void k3_mma(
    const float* __restrict__ AW, const float* __restrict__ Ab, const float* __restrict__ cent)
{
    extern __shared__ char smem[];
    const unsigned sb = smem_u32(smem);
    const int tid = threadIdx.x;
    const int wid = tid >> 5, lane = tid & 31;
    const int bm = blockIdx.x*128, bn = blockIdx.y*128;
    const int wm = wid >> 1, wn = wid & 1;
    const int lrow = lane & 15;
    const unsigned lk = (lane >> 4) * 16;
    const int r = tid >> 1, kh = (tid & 1) * 8;
    const float* arow = g_f + (size_t)(bm+r)*D_;
    const float* wrow = AW + (size_t)(bn+r)*D_;
    const unsigned soff = (unsigned)(r*48 + kh*2);

    float acc[2][8][4];
    #pragma unroll
    for (int i=0;i<2;i++)
        #pragma unroll
        for (int j=0;j<8;j++)
            #pragma unroll
            for (int q=0;q<4;q++) acc[i][j][q]=0.f;

    float s3p = 0.f;
    float4 av0,av1,bv0,bv1;
    {
        av0 = *(const float4*)(arow+kh); av1 = *(const float4*)(arow+kh+4);
        bv0 = *(const float4*)(wrow+kh); bv1 = *(const float4*)(wrow+kh+4);
        s3p += av0.x*av0.x+av0.y*av0.y+av0.z*av0.z+av0.w*av0.w
             + av1.x*av1.x+av1.y*av1.y+av1.z*av1.z+av1.w*av1.w;
        unsigned ah0=bfp(av0.x,av0.y), ah1=bfp(av0.z,av0.w), ah2=bfp(av1.x,av1.y), ah3=bfp(av1.z,av1.w);
        unsigned bh0=bfp(bv0.x,bv0.y), bh1=bfp(bv0.z,bv0.w), bh2=bfp(bv1.x,bv1.y), bh3=bfp(bv1.z,bv1.w);
        sts128(sb + soff,          ah0,ah1,ah2,ah3);
        sts128(sb + 6144u + soff,  lo_from(av0.x,av0.y,ah0), lo_from(av0.z,av0.w,ah1), lo_from(av1.x,av1.y,ah2), lo_from(av1.z,av1.w,ah3));
        sts128(sb + 12288u + soff, bh0,bh1,bh2,bh3);
        sts128(sb + 18432u + soff, lo_from(bv0.x,bv0.y,bh0), lo_from(bv0.z,bv0.w,bh1), lo_from(bv1.x,bv1.y,bh2), lo_from(bv1.z,bv1.w,bh3));
    }
    __syncthreads();

    for (int kt=0; kt<16; kt++){
        const unsigned base = sb + (unsigned)(kt & 1)*K1_STG;
        const unsigned nbase = sb + (unsigned)((kt & 1)^1)*K1_STG;
        if (kt < 15){
            const int col = (kt+1)*16 + kh;
            av0 = *(const float4*)(arow+col);   av1 = *(const float4*)(arow+col+4);
            bv0 = *(const float4*)(wrow+col);   bv1 = *(const float4*)(wrow+col+4);
            s3p += av0.x*av0.x+av0.y*av0.y+av0.z*av0.z+av0.w*av0.w
                 + av1.x*av1.x+av1.y*av1.y+av1.z*av1.z+av1.w*av1.w;
        }
        unsigned ahi[2][4], alo[2][4];
        #pragma unroll
        for (int mi=0; mi<2; mi++){
            unsigned ad = base + (unsigned)((wm*32 + mi*16 + lrow)*48) + lk;
            ldsm4(ahi[mi], ad);
            ldsm4(alo[mi], ad + 6144u);
        }
        #pragma unroll
        for (int np=0; np<4; np++){
            unsigned bd = base + 12288u + (unsigned)((wn*64 + np*16 + lrow)*48) + lk;
            unsigned bh[4], bl[4];
            ldsm4(bh, bd);
            ldsm4(bl, bd + 6144u);
            #pragma unroll
            for (int mi=0; mi<2; mi++){
                mma16816(acc[mi][2*np],   ahi[mi], bh[0], bh[2]);
                mma16816(acc[mi][2*np+1], ahi[mi], bh[1], bh[3]);
                mma16816(acc[mi][2*np],   alo[mi], bh[0], bh[2]);
                mma16816(acc[mi][2*np+1], alo[mi], bh[1], bh[3]);
                mma16816(acc[mi][2*np],   ahi[mi], bl[0], bl[2]);
                mma16816(acc[mi][2*np+1], ahi[mi], bl[1], bl[3]);
            }
        }
        if (kt < 15){
            unsigned ah0=bfp(av0.x,av0.y), ah1=bfp(av0.z,av0.w), ah2=bfp(av1.x,av1.y), ah3=bfp(av1.z,av1.w);
            unsigned bh0=bfp(bv0.x,bv0.y), bh1=bfp(bv0.z,bv0.w), bh2=bfp(bv1.x,bv1.y), bh3=bfp(bv1.z,bv1.w);
            sts128(nbase + soff,          ah0,ah1,ah2,ah3);
            sts128(nbase + 6144u + soff,  lo_from(av0.x,av0.y,ah0), lo_from(av0.z,av0.w,ah1), lo_from(av1.x,av1.y,ah2), lo_from(av1.z,av1.w,ah3));
            sts128(nbase + 12288u + soff, bh0,bh1,bh2,bh3);
            sts128(nbase + 18432u + soff, lo_from(bv0.x,bv0.y,bh0), lo_from(bv0.z,bv0.w,bh1), lo_from(bv1.x,bv1.y,bh2), lo_from(bv1.z,bv1.w,bh3));
        }
        __syncthreads();
    }

    // ||f||^2 per row (each element loaded once; pair (tid, tid^1) covers a row)
    if (blockIdx.y == 0){
        float s3 = s3p + __shfl_xor_sync(0xffffffffu, s3p, 1);
        if ((tid&1)==0) g_s3[bm+r] = s3;
    }

    // fused epilogue: tanh + (hyp.cent, ||hyp||^2) partials over this block's 128 cols
    float* sp = (float*)smem;          // sp1 [128][2] @0, sp2 [128][2] @256
    const int g = lane >> 2, tg = (lane & 3)*2;
    float cv[16], bvv[16];
    #pragma unroll
    for (int ni=0; ni<8; ni++){
        const int c = bn + wn*64 + ni*8 + tg;
        bvv[2*ni]=Ab[c]; bvv[2*ni+1]=Ab[c+1];
        cv[2*ni]=cent[c]; cv[2*ni+1]=cent[c+1];
    }
    #pragma unroll
    for (int mi=0; mi<2; mi++){
        float p1a=0.f,p2a=0.f,p1b=0.f,p2b=0.f;
        #pragma unroll
        for (int ni=0; ni<8; ni++){
            float h0 = ftanh(acc[mi][ni][0]+bvv[2*ni]);
            float h1 = ftanh(acc[mi][ni][1]+bvv[2*ni+1]);
            p1a += h0*cv[2*ni]+h1*cv[2*ni+1]; p2a += h0*h0+h1*h1;
            float h2 = ftanh(acc[mi][ni][2]+bvv[2*ni]);
            float h3 = ftanh(acc[mi][ni][3]+bvv[2*ni+1]);
            p1b += h2*cv[2*ni]+h3*cv[2*ni+1]; p2b += h2*h2+h3*h3;
        }
        #pragma unroll
        for (int o=1; o<=2; o<<=1){
            p1a += __shfl_xor_sync(0xffffffffu,p1a,o);
            p2a += __shfl_xor_sync(0xffffffffu,p2a,o);
            p1b += __shfl_xor_sync(0xffffffffu,p1b,o);
            p2b += __shfl_xor_sync(0xffffffffu,p2b,o);
        }
        if ((lane&3)==0){
            int lr = wm*32 + mi*16 + g;
            sp[lr*2+wn] = p1a;        sp[256 + lr*2+wn] = p2a;
            sp[(lr+8)*2+wn] = p1b;    sp[256 + (lr+8)*2+wn] = p2b;
        }
    }
    __syncthreads();
    if (tid < 128){
        g_s1p[(size_t)blockIdx.y*M_ + bm + tid] = sp[tid*2] + sp[tid*2+1];
        g_s2p[(size_t)blockIdx.y*M_ + bm + tid] = sp[256+tid*2] + sp[256+tid*2+1];
    }
}

// ================= K4: per-row finalize =================
__global__ __launch_bounds__(256) void k4_fin(const float* __restrict__ cent, const float* __restrict__ beta)
{
    __shared__ float swr[8];
    __shared__ float s_cu, s_suru, s_b;
    const int tid = threadIdx.x;
    { float c = cent[tid]; float v=c*c;
      #pragma unroll
      for (int o=16;o;o>>=1) v += __shfl_xor_sync(0xffffffffu, v, o);
      if ((tid&31)==0) swr[tid>>5]=v; }
    __syncthreads();
    if (tid==0){
        float s=0;
        #pragma unroll
        for (int i=0;i<8;i++) s+=swr[i];
        float ru = sqrtf(s);
        s_cu = coshf(ru); s_suru = sinhf(ru)/ru; s_b = beta[0];
    }
    __syncthreads();
    const size_t m = (size_t)blockIdx.x*256 + tid;
    float s1 = g_s1p[m] + g_s1p[M_+m];
    float s2 = g_s2p[m] + g_s2p[M_+m];
    float s3 = g_s3[m];
    float rr = sqrtf(s2);
    float x = coshf(rr)*s_cu - (sinhf(rr)/rr)*s_suru*s1;
    x = fminf(fmaxf(x, 1.f+1e-7f), 1e16f);
    float dist = logf(x) + log1pf(sqrtf(x*x - 1.f + 1e-7f)/x);
    float rf = sqrtf(s3);
    float th = tanhf(rf);
    float gsq = 1.f - th*th;
    gsq = fminf(fmaxf(gsq, 1e-7f), 1.f-1e-7f);
    float gam = 1.f/sqrtf(gsq);
    gam = fminf(fmaxf(gam, 1.f+1e-7f), 1e16f);
    g_coef[m] = expf(-s_b*dist)*gam;
    g_q[m] = th/rf;
}

// ================= K5: pooling =================
__global__ __launch_bounds__(256) void k5_pool(float* __restrict__ out)
{
    __shared__ float cq[T_];
    __shared__ float sden;
    const int b = blockIdx.x, tid = threadIdx.x;
    if (tid < T_) cq[tid] = g_coef[tid*B_ + b];
    __syncthreads();
    if (tid==0){ float s=0; for (int t2=0;t2<T_;t2++) s+=cq[t2]; sden=s; }
    __syncthreads();
    if (tid < T_) cq[tid] = cq[tid]*g_q[tid*B_ + b]/sden;
    __syncthreads();
    float acc = 0.f;
    for (int t2=0;t2<T_;t2++)
        acc += cq[t2]*g_f[((size_t)t2*B_ + b)*D_ + tid];
    out[(size_t)b*D_ + tid] = acc;
}

extern "C" void kernel_launch(void* const* d_in, const int* in_sizes, int n_in,
                              void* d_out, int out_size)
{
    const int*   tok  = (const int*)d_in[0];
    const float* hid  = (const float*)d_in[1];
    const float* emb  = (const float*)d_in[2];
    const float* Wif  = (const float*)d_in[3];
    const float* Whf  = (const float*)d_in[4];
    const float* bif  = (const float*)d_in[5];
    const float* bhf  = (const float*)d_in[6];
    const float* Wib  = (const float*)d_in[7];
    const float* Whb  = (const float*)d_in[8];
    const float* bib  = (const float*)d_in[9];
    const float* bhb  = (const float*)d_in[10];
    const float* AW   = (const float*)d_in[11];
    const float* Ab   = (const float*)d_in[12];
    const float* cent = (const float*)d_in[13];
    const float* beta = (const float*)d_in[14];
    float* out = (float*)d_out;

    cudaFuncSetAttribute(k1_mma, cudaFuncAttributeMaxDynamicSharedMemorySize, K1_SMEM);
    cudaFuncSetAttribute(k2_gru, cudaFuncAttributeMaxDynamicSharedMemorySize, K2_SMEM);
    cudaFuncSetAttribute(k3_mma, cudaFuncAttributeMaxDynamicSharedMemorySize, K3_SMEM);

    k1_mma<<<dim3(512,6),256,K1_SMEM>>>(tok, emb, Wif, Wib, bif, bib);
    k2_gru<<<dim3(64,2),256,K2_SMEM>>>(hid, Whf, Whb, bhf, bhb, out + (size_t)B_*D_);
    k3_mma<<<dim3(512,2),256,K3_SMEM>>>(AW, Ab, cent);
    k4_fin<<<256,256>>>(cent, beta);
    k5_pool<<<512,256>>>(out);
}

// round 11
// speedup vs baseline: 1.7266x; 1.0215x over previous
#include <cuda_runtime.h>
#include <cuda_bf16.h>
#include <cstdint>

#define T_ 128
#define B_ 512
#define H_ 128
#define EMBD 300
#define D_ 256
#define G3 384
#define M_ (T_*B_)

__device__ float g_Pf[(size_t)M_*G3];
__device__ float g_Pb[(size_t)M_*G3];
__device__ float g_f[(size_t)M_*D_];
__device__ float g_s1p[2*M_];
__device__ float g_s2p[2*M_];
__device__ float g_s3[M_];
__device__ float g_coef[M_];
__device__ float g_q[M_];
__device__ float g_dummy[4];

typedef unsigned long long ull;
__device__ __forceinline__ void fma2(ull&c, ull a, ull b){ asm("fma.rn.f32x2 %0,%1,%2,%0;":"+l"(c):"l"(a),"l"(b)); }
__device__ __forceinline__ void add2(ull&c, ull a){ asm("add.rn.f32x2 %0,%0,%1;":"+l"(c):"l"(a)); }
__device__ __forceinline__ ull pk2(float lo,float hi){ ull r; asm("mov.b64 %0,{%1,%2};":"=l"(r):"f"(lo),"f"(hi)); return r; }
__device__ __forceinline__ float2 upk2(ull v){ float2 r; asm("mov.b64 {%0,%1},%2;":"=f"(r.x),"=f"(r.y):"l"(v)); return r; }
__device__ __forceinline__ float fsigm(float x){ return __fdividef(1.f, 1.f + __expf(-x)); }
__device__ __forceinline__ float ftanh(float x){ float e = __expf(2.f*x); return 1.f - __fdividef(2.f, e + 1.f); }

__device__ __forceinline__ unsigned smem_u32(const void* p){
    unsigned a; asm("{ .reg .u64 t; cvta.to.shared.u64 t, %1; cvt.u32.u64 %0, t; }":"=r"(a):"l"(p)); return a;
}
__device__ __forceinline__ unsigned bfp(float a, float b){ unsigned r; asm("cvt.rn.bf16x2.f32 %0,%1,%2;":"=r"(r):"f"(b),"f"(a)); return r; }
__device__ __forceinline__ unsigned lo_from(float a, float b, unsigned hp){
    float ha = __uint_as_float(hp << 16);
    float hb = __uint_as_float(hp & 0xffff0000u);
    return bfp(a - ha, b - hb);
}
__device__ __forceinline__ void sts128(unsigned addr, unsigned x, unsigned y, unsigned z, unsigned w){
    asm volatile("st.shared.v4.b32 [%0], {%1,%2,%3,%4};"::"r"(addr),"r"(x),"r"(y),"r"(z),"r"(w):"memory");
}
__device__ __forceinline__ void ldsm4(unsigned* r, unsigned addr){
    asm volatile("ldmatrix.sync.aligned.m8n8.x4.shared.b16 {%0,%1,%2,%3}, [%4];"
        : "=r"(r[0]),"=r"(r[1]),"=r"(r[2]),"=r"(r[3]) : "r"(addr));
}
__device__ __forceinline__ void mma16816(float* d, const unsigned* a, unsigned b0, unsigned b1){
    asm volatile("mma.sync.aligned.m16n8k16.row.col.f32.bf16.bf16.f32 "
        "{%0,%1,%2,%3}, {%4,%5,%6,%7}, {%8,%9}, {%0,%1,%2,%3};"
        : "+f"(d[0]),"+f"(d[1]),"+f"(d[2]),"+f"(d[3])
        : "r"(a[0]),"r"(a[1]),"r"(a[2]),"r"(a[3]), "r"(b0),"r"(b1));
}

// dummy: shifts the fixed ncu capture slot so k1_mma gets profiled
__global__ void kd_nop(int which){ if (threadIdx.x==0 && blockIdx.x==0) g_dummy[which] = 0.f; }

// ================= K1: HMMA bf16-split GEMM =================
#define K1_STG 24576u
#define K1_SMEM (2*24576 + 512)

__global__ __launch_bounds__(256,2) void k1_mma(
    const int* __restrict__ tok, const float* __restrict__ emb,
    const float* __restrict__ Wf, const float* __restrict__ Wb,
    const float* __restrict__ bf, const float* __restrict__ bb)
{
    extern __shared__ char smem[];
    const unsigned sb = smem_u32(smem);
    int* toks = (int*)(smem + 2*24576);
    const int tid = threadIdx.x;
    const int wid = tid >> 5, lane = tid & 31;
    const int bm = blockIdx.x*128, bn = blockIdx.y*128;
    if (tid < 128) toks[tid] = tok[bm + tid];
    __syncthreads();

    const int wm = wid >> 1, wn = wid & 1;
    const int lrow = lane & 15;
    const unsigned lk = (lane >> 4) * 16;
    const int r = tid >> 1, kh = (tid & 1) * 8;
    const float* arow = emb + (size_t)toks[r]*EMBD;
    const int ng = bn + r;
    const float* wrow = (ng < G3) ? (Wf + (size_t)ng*EMBD) : (Wb + (size_t)(ng-G3)*EMBD);
    const unsigned soff = (unsigned)(r*48 + kh*2);

    float acc[2][8][4];
    #pragma unroll
    for (int i=0;i<2;i++)
        #pragma unroll
        for (int j=0;j<8;j++)
            #pragma unroll
            for (int q=0;q<4;q++) acc[i][j][q]=0.f;

    float4 av0,av1,bv0,bv1;
    {
        av0 = *(const float4*)(arow+kh); av1 = *(const float4*)(arow+kh+4);
        bv0 = *(const float4*)(wrow+kh); bv1 = *(const float4*)(wrow+kh+4);
        unsigned ah0=bfp(av0.x,av0.y), ah1=bfp(av0.z,av0.w), ah2=bfp(av1.x,av1.y), ah3=bfp(av1.z,av1.w);
        unsigned bh0=bfp(bv0.x,bv0.y), bh1=bfp(bv0.z,bv0.w), bh2=bfp(bv1.x,bv1.y), bh3=bfp(bv1.z,bv1.w);
        sts128(sb + soff,          ah0,ah1,ah2,ah3);
        sts128(sb + 6144u + soff,  lo_from(av0.x,av0.y,ah0), lo_from(av0.z,av0.w,ah1), lo_from(av1.x,av1.y,ah2), lo_from(av1.z,av1.w,ah3));
        sts128(sb + 12288u + soff, bh0,bh1,bh2,bh3);
        sts128(sb + 18432u + soff, lo_from(bv0.x,bv0.y,bh0), lo_from(bv0.z,bv0.w,bh1), lo_from(bv1.x,bv1.y,bh2), lo_from(bv1.z,bv1.w,bh3));
    }
    __syncthreads();

    for (int kt=0; kt<19; kt++){
        const unsigned base = sb + (unsigned)(kt & 1)*K1_STG;
        const unsigned nbase = sb + (unsigned)((kt & 1)^1)*K1_STG;
        if (kt < 18){
            const int col = (kt+1)*16 + kh;
            const float4 z4 = make_float4(0.f,0.f,0.f,0.f);
            av0 = (col   < EMBD) ? *(const float4*)(arow+col)   : z4;
            av1 = (col+4 < EMBD) ? *(const float4*)(arow+col+4) : z4;
            bv0 = (col   < EMBD) ? *(const float4*)(wrow+col)   : z4;
            bv1 = (col+4 < EMBD) ? *(const float4*)(wrow+col+4) : z4;
        }
        unsigned ahi[2][4], alo[2][4];
        #pragma unroll
        for (int mi=0; mi<2; mi++){
            unsigned ad = base + (unsigned)((wm*32 + mi*16 + lrow)*48) + lk;
            ldsm4(ahi[mi], ad);
            ldsm4(alo[mi], ad + 6144u);
        }
        #pragma unroll
        for (int np=0; np<4; np++){
            unsigned bd = base + 12288u + (unsigned)((wn*64 + np*16 + lrow)*48) + lk;
            unsigned bh[4], bl[4];
            ldsm4(bh, bd);
            ldsm4(bl, bd + 6144u);
            #pragma unroll
            for (int mi=0; mi<2; mi++){
                mma16816(acc[mi][2*np],   ahi[mi], bh[0], bh[2]);
                mma16816(acc[mi][2*np+1], ahi[mi], bh[1], bh[3]);
                mma16816(acc[mi][2*np],   alo[mi], bh[0], bh[2]);
                mma16816(acc[mi][2*np+1], alo[mi], bh[1], bh[3]);
                mma16816(acc[mi][2*np],   ahi[mi], bl[0], bl[2]);
                mma16816(acc[mi][2*np+1], ahi[mi], bl[1], bl[3]);
            }
        }
        if (kt < 18){
            unsigned ah0=bfp(av0.x,av0.y), ah1=bfp(av0.z,av0.w), ah2=bfp(av1.x,av1.y), ah3=bfp(av1.z,av1.w);
            unsigned bh0=bfp(bv0.x,bv0.y), bh1=bfp(bv0.z,bv0.w), bh2=bfp(bv1.x,bv1.y), bh3=bfp(bv1.z,bv1.w);
            sts128(nbase + soff,          ah0,ah1,ah2,ah3);
            sts128(nbase + 6144u + soff,  lo_from(av0.x,av0.y,ah0), lo_from(av0.z,av0.w,ah1), lo_from(av1.x,av1.y,ah2), lo_from(av1.z,av1.w,ah3));
            sts128(nbase + 12288u + soff, bh0,bh1,bh2,bh3);
            sts128(nbase + 18432u + soff, lo_from(bv0.x,bv0.y,bh0), lo_from(bv0.z,bv0.w,bh1), lo_from(bv1.x,bv1.y,bh2), lo_from(bv1.z,bv1.w,bh3));
        }
        __syncthreads();
    }

    float* dst; const float* bias_; int nb;
    if (bn < G3){ dst = g_Pf; nb = bn; bias_ = bf; } else { dst = g_Pb; nb = bn - G3; bias_ = bb; }
    const int g = lane >> 2, tg = (lane & 3)*2;
    #pragma unroll
    for (int mi=0; mi<2; mi++){
        const int row = bm + wm*32 + mi*16 + g;
        #pragma unroll
        for (int ni=0; ni<8; ni++){
            const int c = wn*64 + ni*8 + tg;
            const float b0 = bias_[nb + c], b1 = bias_[nb + c + 1];
            float2 v0 = make_float2(acc[mi][ni][0] + b0, acc[mi][ni][1] + b1);
            float2 v1 = make_float2(acc[mi][ni][2] + b0, acc[mi][ni][3] + b1);
            *(float2*)(dst + (size_t)row*G3 + nb + c) = v0;
            *(float2*)(dst + (size_t)(row+8)*G3 + nb + c) = v1;
        }
    }
}

// ================= K2: GRU, grid(64,2), 256 threads, symmetric k/batch split =================
#define K2_SMEM 212992

__global__ __launch_bounds__(256) void k2_gru(
    const float* __restrict__ hidden,
    const float* __restrict__ Whf, const float* __restrict__ Whb,
    const float* __restrict__ bhf, const float* __restrict__ bhb,
    float* __restrict__ outH)
{
    extern __shared__ float sm[];
    float2* wrz = (float2*)sm;
    float*  wn  = sm + 32768;
    float*  hs  = sm + 49152;
    ull*    pbuf= (ull*)(sm + 50176);

    const int dir = blockIdx.y, b0 = blockIdx.x*8;
    const int tid = threadIdx.x;
    const int t = tid & 127;
    const int half = tid >> 7;
    const int kbase = half * 64;
    const float* W  = dir? Whb : Whf;
    const float* bh = dir? bhb : bhf;
    const float* P  = dir? g_Pb : g_Pf;

    for (int idx = tid; idx < 128*G3; idx += 256){
        int j = idx >> 7, k = idx & 127;
        float w = W[(size_t)j*H_ + k];
        if (j < 128)      ((float*)wrz)[(k*128 + j)*2]       = w;
        else if (j < 256) ((float*)wrz)[(k*128 + (j-128))*2+1] = w;
        else              wn[k*128 + (j-256)] = w;
    }
    float hreg[4];
    #pragma unroll
    for (int j=0;j<4;j++){
        int bi = half*4 + j;
        float hv = hidden[(size_t)dir*B_*H_ + (size_t)(b0+bi)*H_ + t];
        hreg[j]=hv; hs[t*8+bi]=hv;
    }
    const float br=bh[t], bz=bh[H_+t], bn2=bh[2*H_+t];
    __syncthreads();
    const longlong2* h128 = (const longlong2*)hs;
    const int po = 2 - 2*half;
    const int pkp = 2*half;

    for (int s=0;s<T_;s++){
        const int tt = dir ? (T_-1-s) : s;
        const float* prow = P + ((size_t)tt*B_ + b0)*G3;
        float xr[4],xz[4],xn[4];
        #pragma unroll
        for (int j=0;j<4;j++){
            int bi = half*4 + j;
            xr[j]=prow[bi*G3+t]; xz[j]=prow[bi*G3+H_+t]; xn[j]=prow[bi*G3+2*H_+t];
        }
        ull ar[4],az[4],an[4];
        #pragma unroll
        for (int p=0;p<4;p++){ ar[p]=0; az[p]=0; an[p]=0; }
        #pragma unroll 4
        for (int k=kbase; k<kbase+64; k++){
            float2 wv = wrz[k*128+t];
            float wnv = wn[k*128+t];
            ull p0=pk2(wv.x,wv.x), p1=pk2(wv.y,wv.y), p2=pk2(wnv,wnv);
            longlong2 hA = h128[k*2], hB = h128[k*2+1];
            ull h0=(ull)hA.x, h1=(ull)hA.y, h2=(ull)hB.x, h3=(ull)hB.y;
            fma2(ar[0],h0,p0); fma2(ar[1],h1,p0); fma2(ar[2],h2,p0); fma2(ar[3],h3,p0);
            fma2(az[0],h0,p1); fma2(az[1],h1,p1); fma2(az[2],h2,p1); fma2(az[3],h3,p1);
            fma2(an[0],h0,p2); fma2(an[1],h1,p2); fma2(an[2],h2,p2); fma2(an[3],h3,p2);
        }
        {
            ull* ms = pbuf + (t*2 + half)*6;
            ms[0]=ar[po]; ms[1]=ar[po+1]; ms[2]=az[po]; ms[3]=az[po+1]; ms[4]=an[po]; ms[5]=an[po+1];
        }
        __syncthreads();
        {
            const ull* os = pbuf + (t*2 + (half^1))*6;
            add2(ar[pkp],os[0]); add2(ar[pkp+1],os[1]);
            add2(az[pkp],os[2]); add2(az[pkp+1],os[3]);
            add2(an[pkp],os[4]); add2(an[pkp+1],os[5]);
        }
        #pragma unroll
        for (int j=0;j<4;j++){
            int bi = half*4 + j;
            int p = pkp + (j>>1);
            float2 gr=upk2(ar[p]), gz=upk2(az[p]), gn=upk2(an[p]);
            float grv=(j&1)?gr.y:gr.x, gzv=(j&1)?gz.y:gz.x, gnv=(j&1)?gn.y:gn.x;
            float rg = fsigm(xr[j] + grv + br);
            float zg = fsigm(xz[j] + gzv + bz);
            float ng = ftanh(xn[j] + rg*(gnv + bn2));
            float h2 = (1.f-zg)*ng + zg*hreg[j];
            hreg[j]=h2; hs[t*8+bi]=h2;
            g_f[((size_t)tt*B_ + (b0+bi))*D_ + dir*H_ + t] = h2;
        }
        __syncthreads();
    }
    #pragma unroll
    for (int j=0;j<4;j++){
        int bi = half*4 + j;
        outH[(size_t)dir*B_*H_ + (size_t)(b0+bi)*H_ + t] = hreg[j];
    }
}

// ============ K3: HMMA bf16-split, tanh epilogue fused with row reductions ============
#define K3_SMEM (2*24576 + 2048)

__global__ __launch_bounds__(256,2) void k3_mma(
    const float* __restrict__ AW, const float* __restrict__ Ab, const float* __restrict__ cent)
{
    extern __shared__ char smem[];
    const unsigned sb = smem_u32(smem);
    const int tid = threadIdx.x;
    const int wid = tid >> 5, lane = tid & 31;
    const int bm = blockIdx.x*128, bn = blockIdx.y*128;
    const int wm = wid >> 1, wn = wid & 1;
    const int lrow = lane & 15;
    const unsigned lk = (lane >> 4) * 16;
    const int r = tid >> 1, kh = (tid & 1) * 8;
    const float* arow = g_f + (size_t)(bm+r)*D_;
    const float* wrow = AW + (size_t)(bn+r)*D_;
    const unsigned soff = (unsigned)(r*48 + kh*2);

    float acc[2][8][4];
    #pragma unroll
    for (int i=0;i<2;i++)
        #pragma unroll
        for (int j=0;j<8;j++)
            #pragma unroll
            for (int q=0;q<4;q++) acc[i][j][q]=0.f;

    float s3p = 0.f;
    float4 av0,av1,bv0,bv1;
    {
        av0 = *(const float4*)(arow+kh); av1 = *(const float4*)(arow+kh+4);
        bv0 = *(const float4*)(wrow+kh); bv1 = *(const float4*)(wrow+kh+4);
        s3p += av0.x*av0.x+av0.y*av0.y+av0.z*av0.z+av0.w*av0.w
             + av1.x*av1.x+av1.y*av1.y+av1.z*av1.z+av1.w*av1.w;
        unsigned ah0=bfp(av0.x,av0.y), ah1=bfp(av0.z,av0.w), ah2=bfp(av1.x,av1.y), ah3=bfp(av1.z,av1.w);
        unsigned bh0=bfp(bv0.x,bv0.y), bh1=bfp(bv0.z,bv0.w), bh2=bfp(bv1.x,bv1.y), bh3=bfp(bv1.z,bv1.w);
        sts128(sb + soff,          ah0,ah1,ah2,ah3);
        sts128(sb + 6144u + soff,  lo_from(av0.x,av0.y,ah0), lo_from(av0.z,av0.w,ah1), lo_from(av1.x,av1.y,ah2), lo_from(av1.z,av1.w,ah3));
        sts128(sb + 12288u + soff, bh0,bh1,bh2,bh3);
        sts128(sb + 18432u + soff, lo_from(bv0.x,bv0.y,bh0), lo_from(bv0.z,bv0.w,bh1), lo_from(bv1.x,bv1.y,bh2), lo_from(bv1.z,bv1.w,bh3));
    }
    __syncthreads();

    for (int kt=0; kt<16; kt++){
        const unsigned base = sb + (unsigned)(kt & 1)*K1_STG;
        const unsigned nbase = sb + (unsigned)((kt & 1)^1)*K1_STG;
        if (kt < 15){
            const int col = (kt+1)*16 + kh;
            av0 = *(const float4*)(arow+col);   av1 = *(const float4*)(arow+col+4);
            bv0 = *(const float4*)(wrow+col);   bv1 = *(const float4*)(wrow+col+4);
            s3p += av0.x*av0.x+av0.y*av0.y+av0.z*av0.z+av0.w*av0.w
                 + av1.x*av1.x+av1.y*av1.y+av1.z*av1.z+av1.w*av1.w;
        }
        unsigned ahi[2][4], alo[2][4];
        #pragma unroll
        for (int mi=0; mi<2; mi++){
            unsigned ad = base + (unsigned)((wm*32 + mi*16 + lrow)*48) + lk;
            ldsm4(ahi[mi], ad);
            ldsm4(alo[mi], ad + 6144u);
        }
        #pragma unroll
        for (int np=0; np<4; np++){
            unsigned bd = base + 12288u + (unsigned)((wn*64 + np*16 + lrow)*48) + lk;
            unsigned bh[4], bl[4];
            ldsm4(bh, bd);
            ldsm4(bl, bd + 6144u);
            #pragma unroll
            for (int mi=0; mi<2; mi++){
                mma16816(acc[mi][2*np],   ahi[mi], bh[0], bh[2]);
                mma16816(acc[mi][2*np+1], ahi[mi], bh[1], bh[3]);
                mma16816(acc[mi][2*np],   alo[mi], bh[0], bh[2]);
                mma16816(acc[mi][2*np+1], alo[mi], bh[1], bh[3]);
                mma16816(acc[mi][2*np],   ahi[mi], bl[0], bl[2]);
                mma16816(acc[mi][2*np+1], ahi[mi], bl[1], bl[3]);
            }
        }
        if (kt < 15){
            unsigned ah0=bfp(av0.x,av0.y), ah1=bfp(av0.z,av0.w), ah2=bfp(av1.x,av1.y), ah3=bfp(av1.z,av1.w);
            unsigned bh0=bfp(bv0.x,bv0.y), bh1=bfp(bv0.z,bv0.w), bh2=bfp(bv1.x,bv1.y), bh3=bfp(bv1.z,bv1.w);
            sts128(nbase + soff,          ah0,ah1,ah2,ah3);
            sts128(nbase + 6144u + soff,  lo_from(av0.x,av0.y,ah0), lo_from(av0.z,av0.w,ah1), lo_from(av1.x,av1.y,ah2), lo_from(av1.z,av1.w,ah3));
            sts128(nbase + 12288u + soff, bh0,bh1,bh2,bh3);
            sts128(nbase + 18432u + soff, lo_from(bv0.x,bv0.y,bh0), lo_from(bv0.z,bv0.w,bh1), lo_from(bv1.x,bv1.y,bh2), lo_from(bv1.z,bv1.w,bh3));
        }
        __syncthreads();
    }

    if (blockIdx.y == 0){
        float s3 = s3p + __shfl_xor_sync(0xffffffffu, s3p, 1);
        if ((tid&1)==0) g_s3[bm+r] = s3;
    }

    float* sp = (float*)smem;
    const int g = lane >> 2, tg = (lane & 3)*2;
    float cv[16], bvv[16];
    #pragma unroll
    for (int ni=0; ni<8; ni++){
        const int c = bn + wn*64 + ni*8 + tg;
        bvv[2*ni]=Ab[c]; bvv[2*ni+1]=Ab[c+1];
        cv[2*ni]=cent[c]; cv[2*ni+1]=cent[c+1];
    }
    #pragma unroll
    for (int mi=0; mi<2; mi++){
        float p1a=0.f,p2a=0.f,p1b=0.f,p2b=0.f;
        #pragma unroll
        for (int ni=0; ni<8; ni++){
            float h0 = ftanh(acc[mi][ni][0]+bvv[2*ni]);
            float h1 = ftanh(acc[mi][ni][1]+bvv[2*ni+1]);
            p1a += h0*cv[2*ni]+h1*cv[2*ni+1]; p2a += h0*h0+h1*h1;
            float h2 = ftanh(acc[mi][ni][2]+bvv[2*ni]);
            float h3 = ftanh(acc[mi][ni][3]+bvv[2*ni+1]);
            p1b += h2*cv[2*ni]+h3*cv[2*ni+1]; p2b += h2*h2+h3*h3;
        }
        #pragma unroll
        for (int o=1; o<=2; o<<=1){
            p1a += __shfl_xor_sync(0xffffffffu,p1a,o);
            p2a += __shfl_xor_sync(0xffffffffu,p2a,o);
            p1b += __shfl_xor_sync(0xffffffffu,p1b,o);
            p2b += __shfl_xor_sync(0xffffffffu,p2b,o);
        }
        if ((lane&3)==0){
            int lr = wm*32 + mi*16 + g;
            sp[lr*2+wn] = p1a;        sp[256 + lr*2+wn] = p2a;
            sp[(lr+8)*2+wn] = p1b;    sp[256 + (lr+8)*2+wn] = p2b;
        }
    }
    __syncthreads();
    if (tid < 128){
        g_s1p[(size_t)blockIdx.y*M_ + bm + tid] = sp[tid*2] + sp[tid*2+1];
        g_s2p[(size_t)blockIdx.y*M_ + bm + tid] = sp[256+tid*2] + sp[256+tid*2+1];
    }
}

// ================= K4: per-row finalize =================
__global__ __launch_bounds__(256) void k4_fin(const float* __restrict__ cent, const float* __restrict__ beta)
{
    __shared__ float swr[8];
    __shared__ float s_cu, s_suru, s_b;
    const int tid = threadIdx.x;
    { float c = cent[tid]; float v=c*c;
      #pragma unroll
      for (int o=16;o;o>>=1) v += __shfl_xor_sync(0xffffffffu, v, o);
      if ((tid&31)==0) swr[tid>>5]=v; }
    __syncthreads();
    if (tid==0){
        float s=0;
        #pragma unroll
        for (int i=0;i<8;i++) s+=swr[i];
        float ru = sqrtf(s);
        s_cu = coshf(ru); s_suru = sinhf(ru)/ru; s_b = beta[0];
    }
    __syncthreads();
    const size_t m = (size_t)blockIdx.x*256 + tid;
    float s1 = g_s1p[m] + g_s1p[M_+m];
    float s2 = g_s2p[m] + g_s2p[M_+m];
    float s3 = g_s3[m];
    float rr = sqrtf(s2);
    float x = coshf(rr)*s_cu - (sinhf(rr)/rr)*s_suru*s1;
    x = fminf(fmaxf(x, 1.f+1e-7f), 1e16f);
    float dist = logf(x) + log1pf(sqrtf(x*x - 1.f + 1e-7f)/x);
    float rf = sqrtf(s3);
    float th = tanhf(rf);
    float gsq = 1.f - th*th;
    gsq = fminf(fmaxf(gsq, 1e-7f), 1.f-1e-7f);
    float gam = 1.f/sqrtf(gsq);
    gam = fminf(fmaxf(gam, 1.f+1e-7f), 1e16f);
    g_coef[m] = expf(-s_b*dist)*gam;
    g_q[m] = th/rf;
}

// ================= K5: pooling =================
__global__ __launch_bounds__(256) void k5_pool(float* __restrict__ out)
{
    __shared__ float cq[T_];
    __shared__ float sden;
    const int b = blockIdx.x, tid = threadIdx.x;
    if (tid < T_) cq[tid] = g_coef[tid*B_ + b];
    __syncthreads();
    if (tid==0){ float s=0; for (int t2=0;t2<T_;t2++) s+=cq[t2]; sden=s; }
    __syncthreads();
    if (tid < T_) cq[tid] = cq[tid]*g_q[tid*B_ + b]/sden;
    __syncthreads();
    float acc = 0.f;
    for (int t2=0;t2<T_;t2++)
        acc += cq[t2]*g_f[((size_t)t2*B_ + b)*D_ + tid];
    out[(size_t)b*D_ + tid] = acc;
}

extern "C" void kernel_launch(void* const* d_in, const int* in_sizes, int n_in,
                              void* d_out, int out_size)
{
    const int*   tok  = (const int*)d_in[0];
    const float* hid  = (const float*)d_in[1];
    const float* emb  = (const float*)d_in[2];
    const float* Wif  = (const float*)d_in[3];
    const float* Whf  = (const float*)d_in[4];
    const float* bif  = (const float*)d_in[5];
    const float* bhf  = (const float*)d_in[6];
    const float* Wib  = (const float*)d_in[7];
    const float* Whb  = (const float*)d_in[8];
    const float* bib  = (const float*)d_in[9];
    const float* bhb  = (const float*)d_in[10];
    const float* AW   = (const float*)d_in[11];
    const float* Ab   = (const float*)d_in[12];
    const float* cent = (const float*)d_in[13];
    const float* beta = (const float*)d_in[14];
    float* out = (float*)d_out;

    cudaFuncSetAttribute(k1_mma, cudaFuncAttributeMaxDynamicSharedMemorySize, K1_SMEM);
    cudaFuncSetAttribute(k2_gru, cudaFuncAttributeMaxDynamicSharedMemorySize, K2_SMEM);
    cudaFuncSetAttribute(k3_mma, cudaFuncAttributeMaxDynamicSharedMemorySize, K3_SMEM);

    // 3 dummy launches: shift the fixed ncu capture slot onto k1_mma
    kd_nop<<<1,32>>>(0);
    kd_nop<<<1,32>>>(1);
    kd_nop<<<1,32>>>(2);

    k1_mma<<<dim3(512,6),256,K1_SMEM>>>(tok, emb, Wif, Wib, bif, bib);
    k2_gru<<<dim3(64,2),256,K2_SMEM>>>(hid, Whf, Whb, bhf, bhb, out + (size_t)B_*D_);
    k3_mma<<<dim3(512,2),256,K3_SMEM>>>(AW, Ab, cent);
    k4_fin<<<256,256>>>(cent, beta);
    k5_pool<<<512,256>>>(out);
}

// round 12
// speedup vs baseline: 1.9815x; 1.1476x over previous
#include <cuda_runtime.h>
#include <cuda_bf16.h>
#include <cstdint>

#define T_ 128
#define B_ 512
#define H_ 128
#define EMBD 300
#define D_ 256
#define G3 384
#define M_ (T_*B_)

__device__ float g_Pf[(size_t)M_*G3];
__device__ float g_Pb[(size_t)M_*G3];
__device__ float g_f[(size_t)M_*D_];
__device__ float g_s1p[2*M_];
__device__ float g_s2p[2*M_];
__device__ float g_s3[M_];
__device__ float g_coef[M_];
__device__ float g_q[M_];
__device__ float g_dummy[8];

typedef unsigned long long ull;
__device__ __forceinline__ void fma2(ull&c, ull a, ull b){ asm("fma.rn.f32x2 %0,%1,%2,%0;":"+l"(c):"l"(a),"l"(b)); }
__device__ __forceinline__ ull pk2(float lo,float hi){ ull r; asm("mov.b64 %0,{%1,%2};":"=l"(r):"f"(lo),"f"(hi)); return r; }
__device__ __forceinline__ float2 upk2(ull v){ float2 r; asm("mov.b64 {%0,%1},%2;":"=f"(r.x),"=f"(r.y):"l"(v)); return r; }
__device__ __forceinline__ float fsigm(float x){ return __fdividef(1.f, 1.f + __expf(-x)); }
__device__ __forceinline__ float ftanh(float x){ float e = __expf(2.f*x); return 1.f - __fdividef(2.f, e + 1.f); }

__device__ __forceinline__ unsigned smem_u32(const void* p){
    unsigned a; asm("{ .reg .u64 t; cvta.to.shared.u64 t, %1; cvt.u32.u64 %0, t; }":"=r"(a):"l"(p)); return a;
}
__device__ __forceinline__ unsigned bfp(float a, float b){ unsigned r; asm("cvt.rn.bf16x2.f32 %0,%1,%2;":"=r"(r):"f"(b),"f"(a)); return r; }
__device__ __forceinline__ unsigned lo_from(float a, float b, unsigned hp){
    float ha = __uint_as_float(hp << 16);
    float hb = __uint_as_float(hp & 0xffff0000u);
    return bfp(a - ha, b - hb);
}
__device__ __forceinline__ void sts128(unsigned addr, unsigned x, unsigned y, unsigned z, unsigned w){
    asm volatile("st.shared.v4.b32 [%0], {%1,%2,%3,%4};"::"r"(addr),"r"(x),"r"(y),"r"(z),"r"(w):"memory");
}
__device__ __forceinline__ void ldsm4(unsigned* r, unsigned addr){
    asm volatile("ldmatrix.sync.aligned.m8n8.x4.shared.b16 {%0,%1,%2,%3}, [%4];"
        : "=r"(r[0]),"=r"(r[1]),"=r"(r[2]),"=r"(r[3]) : "r"(addr));
}
__device__ __forceinline__ void mma16816(float* d, const unsigned* a, unsigned b0, unsigned b1){
    asm volatile("mma.sync.aligned.m16n8k16.row.col.f32.bf16.bf16.f32 "
        "{%0,%1,%2,%3}, {%4,%5,%6,%7}, {%8,%9}, {%0,%1,%2,%3};"
        : "+f"(d[0]),"+f"(d[1]),"+f"(d[2]),"+f"(d[3])
        : "r"(a[0]),"r"(a[1]),"r"(a[2]),"r"(a[3]), "r"(b0),"r"(b1));
}

// dummy: shifts the fixed ncu capture slot (4 now -> captures k2_gru)
__global__ void kd_nop(int which){ if (threadIdx.x==0 && blockIdx.x==0) g_dummy[which] = 0.f; }

// ================= K1: HMMA bf16-split GEMM =================
#define K1_STG 24576u
#define K1_SMEM (2*24576 + 512)

__global__ __launch_bounds__(256,2) void k1_mma(
    const int* __restrict__ tok, const float* __restrict__ emb,
    const float* __restrict__ Wf, const float* __restrict__ Wb,
    const float* __restrict__ bf, const float* __restrict__ bb)
{
    extern __shared__ char smem[];
    const unsigned sb = smem_u32(smem);
    int* toks = (int*)(smem + 2*24576);
    const int tid = threadIdx.x;
    const int wid = tid >> 5, lane = tid & 31;
    const int bm = blockIdx.x*128, bn = blockIdx.y*128;
    if (tid < 128) toks[tid] = tok[bm + tid];
    __syncthreads();

    const int wm = wid >> 1, wn = wid & 1;
    const int lrow = lane & 15;
    const unsigned lk = (lane >> 4) * 16;
    const int r = tid >> 1, kh = (tid & 1) * 8;
    const float* arow = emb + (size_t)toks[r]*EMBD;
    const int ng = bn + r;
    const float* wrow = (ng < G3) ? (Wf + (size_t)ng*EMBD) : (Wb + (size_t)(ng-G3)*EMBD);
    const unsigned soff = (unsigned)(r*48 + kh*2);

    float acc[2][8][4];
    #pragma unroll
    for (int i=0;i<2;i++)
        #pragma unroll
        for (int j=0;j<8;j++)
            #pragma unroll
            for (int q=0;q<4;q++) acc[i][j][q]=0.f;

    float4 av0,av1,bv0,bv1;
    {
        av0 = *(const float4*)(arow+kh); av1 = *(const float4*)(arow+kh+4);
        bv0 = *(const float4*)(wrow+kh); bv1 = *(const float4*)(wrow+kh+4);
        unsigned ah0=bfp(av0.x,av0.y), ah1=bfp(av0.z,av0.w), ah2=bfp(av1.x,av1.y), ah3=bfp(av1.z,av1.w);
        unsigned bh0=bfp(bv0.x,bv0.y), bh1=bfp(bv0.z,bv0.w), bh2=bfp(bv1.x,bv1.y), bh3=bfp(bv1.z,bv1.w);
        sts128(sb + soff,          ah0,ah1,ah2,ah3);
        sts128(sb + 6144u + soff,  lo_from(av0.x,av0.y,ah0), lo_from(av0.z,av0.w,ah1), lo_from(av1.x,av1.y,ah2), lo_from(av1.z,av1.w,ah3));
        sts128(sb + 12288u + soff, bh0,bh1,bh2,bh3);
        sts128(sb + 18432u + soff, lo_from(bv0.x,bv0.y,bh0), lo_from(bv0.z,bv0.w,bh1), lo_from(bv1.x,bv1.y,bh2), lo_from(bv1.z,bv1.w,bh3));
    }
    __syncthreads();

    for (int kt=0; kt<19; kt++){
        const unsigned base = sb + (unsigned)(kt & 1)*K1_STG;
        const unsigned nbase = sb + (unsigned)((kt & 1)^1)*K1_STG;
        if (kt < 18){
            const int col = (kt+1)*16 + kh;
            const float4 z4 = make_float4(0.f,0.f,0.f,0.f);
            av0 = (col   < EMBD) ? *(const float4*)(arow+col)   : z4;
            av1 = (col+4 < EMBD) ? *(const float4*)(arow+col+4) : z4;
            bv0 = (col   < EMBD) ? *(const float4*)(wrow+col)   : z4;
            bv1 = (col+4 < EMBD) ? *(const float4*)(wrow+col+4) : z4;
        }
        unsigned ahi[2][4], alo[2][4];
        #pragma unroll
        for (int mi=0; mi<2; mi++){
            unsigned ad = base + (unsigned)((wm*32 + mi*16 + lrow)*48) + lk;
            ldsm4(ahi[mi], ad);
            ldsm4(alo[mi], ad + 6144u);
        }
        #pragma unroll
        for (int np=0; np<4; np++){
            unsigned bd = base + 12288u + (unsigned)((wn*64 + np*16 + lrow)*48) + lk;
            unsigned bh[4], bl[4];
            ldsm4(bh, bd);
            ldsm4(bl, bd + 6144u);
            #pragma unroll
            for (int mi=0; mi<2; mi++){
                mma16816(acc[mi][2*np],   ahi[mi], bh[0], bh[2]);
                mma16816(acc[mi][2*np+1], ahi[mi], bh[1], bh[3]);
                mma16816(acc[mi][2*np],   alo[mi], bh[0], bh[2]);
                mma16816(acc[mi][2*np+1], alo[mi], bh[1], bh[3]);
                mma16816(acc[mi][2*np],   ahi[mi], bl[0], bl[2]);
                mma16816(acc[mi][2*np+1], ahi[mi], bl[1], bl[3]);
            }
        }
        if (kt < 18){
            unsigned ah0=bfp(av0.x,av0.y), ah1=bfp(av0.z,av0.w), ah2=bfp(av1.x,av1.y), ah3=bfp(av1.z,av1.w);
            unsigned bh0=bfp(bv0.x,bv0.y), bh1=bfp(bv0.z,bv0.w), bh2=bfp(bv1.x,bv1.y), bh3=bfp(bv1.z,bv1.w);
            sts128(nbase + soff,          ah0,ah1,ah2,ah3);
            sts128(nbase + 6144u + soff,  lo_from(av0.x,av0.y,ah0), lo_from(av0.z,av0.w,ah1), lo_from(av1.x,av1.y,ah2), lo_from(av1.z,av1.w,ah3));
            sts128(nbase + 12288u + soff, bh0,bh1,bh2,bh3);
            sts128(nbase + 18432u + soff, lo_from(bv0.x,bv0.y,bh0), lo_from(bv0.z,bv0.w,bh1), lo_from(bv1.x,bv1.y,bh2), lo_from(bv1.z,bv1.w,bh3));
        }
        __syncthreads();
    }

    float* dst; const float* bias_; int nb;
    if (bn < G3){ dst = g_Pf; nb = bn; bias_ = bf; } else { dst = g_Pb; nb = bn - G3; bias_ = bb; }
    const int g = lane >> 2, tg = (lane & 3)*2;
    #pragma unroll
    for (int mi=0; mi<2; mi++){
        const int row = bm + wm*32 + mi*16 + g;
        #pragma unroll
        for (int ni=0; ni<8; ni++){
            const int c = wn*64 + ni*8 + tg;
            const float b0 = bias_[nb + c], b1 = bias_[nb + c + 1];
            float2 v0 = make_float2(acc[mi][ni][0] + b0, acc[mi][ni][1] + b1);
            float2 v1 = make_float2(acc[mi][ni][2] + b0, acc[mi][ni][3] + b1);
            *(float2*)(dst + (size_t)row*G3 + nb + c) = v0;
            *(float2*)(dst + (size_t)(row+8)*G3 + nb + c) = v1;
        }
    }
}

// ===== K2: GRU, grid(64,2), 256 threads. Partner-in-warp k-split (shfl combine), =====
// ===== double-buffered h state, ONE barrier per step, x-prefetch.                =====
// smem: wrz float2[k][t] @0 (128KB), wn [k][t] @32768 floats (64KB), hs[2][1024] @49152 (8KB)
#define K2_SMEM (128*G3*4 + 2*128*8*4)

__global__ __launch_bounds__(256) void k2_gru(
    const float* __restrict__ hidden,
    const float* __restrict__ Whf, const float* __restrict__ Whb,
    const float* __restrict__ bhf, const float* __restrict__ bhb,
    float* __restrict__ outH)
{
    extern __shared__ float sm[];
    float2* wrz = (float2*)sm;
    float*  wn  = sm + 32768;
    float*  hsA = sm + 49152;     // [2][128*8]

    const int dir = blockIdx.y, b0 = blockIdx.x*8;
    const int tid = threadIdx.x;
    const int lane = tid & 31, wid = tid >> 5;
    const int t = wid*16 + (lane & 15);   // hidden index
    const int half = lane >> 4;           // k-half; partner = lane^16 (same t)
    const int kbase = half * 64;
    const float* W  = dir? Whb : Whf;
    const float* bh = dir? bhb : bhf;
    const float* P  = dir? g_Pb : g_Pf;

    for (int idx = tid; idx < 128*G3; idx += 256){
        int j = idx >> 7, k = idx & 127;
        float w = W[(size_t)j*H_ + k];
        if (j < 128)      ((float*)wrz)[(k*128 + j)*2]         = w;
        else if (j < 256) ((float*)wrz)[(k*128 + (j-128))*2+1] = w;
        else              wn[k*128 + (j-256)] = w;
    }
    float hreg[4];
    #pragma unroll
    for (int j=0;j<4;j++){
        int bi = half*4 + j;
        float hv = hidden[(size_t)dir*B_*H_ + (size_t)(b0+bi)*H_ + t];
        hreg[j]=hv; hsA[t*8+bi]=hv;
    }
    const float br=bh[t], bz=bh[H_+t], bn2=bh[2*H_+t];

    // preload x for step 0
    float xr[4],xz[4],xn[4];
    {
        const int tt0 = dir ? (T_-1) : 0;
        const float* prow = P + ((size_t)tt0*B_ + b0)*G3;
        #pragma unroll
        for (int j=0;j<4;j++){
            int bi = half*4 + j;
            xr[j]=prow[bi*G3+t]; xz[j]=prow[bi*G3+H_+t]; xn[j]=prow[bi*G3+2*H_+t];
        }
    }
    __syncthreads();

    int cur = 0;
    for (int s=0;s<T_;s++){
        const int tt = dir ? (T_-1-s) : s;
        const longlong2* h128 = (const longlong2*)(hsA + cur*1024);
        ull ar[4],az[4],an[4];
        #pragma unroll
        for (int p=0;p<4;p++){ ar[p]=0; az[p]=0; an[p]=0; }
        #pragma unroll 4
        for (int k=kbase; k<kbase+64; k++){
            float2 wv = wrz[k*128+t];
            float wnv = wn[k*128+t];
            ull p0=pk2(wv.x,wv.x), p1=pk2(wv.y,wv.y), p2=pk2(wnv,wnv);
            longlong2 hA = h128[k*2], hB = h128[k*2+1];
            ull h0=(ull)hA.x, h1=(ull)hA.y, h2=(ull)hB.x, h3=(ull)hB.y;
            fma2(ar[0],h0,p0); fma2(ar[1],h1,p0); fma2(ar[2],h2,p0); fma2(ar[3],h3,p0);
            fma2(az[0],h0,p1); fma2(az[1],h1,p1); fma2(az[2],h2,p1); fma2(az[3],h3,p1);
            fma2(an[0],h0,p2); fma2(an[1],h1,p2); fma2(an[2],h2,p2); fma2(an[3],h3,p2);
        }
        // combine with partner lane (lane^16): full sums in all pairs
        #pragma unroll
        for (int p=0;p<4;p++){
            float2 v;
            v=upk2(ar[p]); v.x+=__shfl_xor_sync(0xffffffffu,v.x,16); v.y+=__shfl_xor_sync(0xffffffffu,v.y,16); ar[p]=pk2(v.x,v.y);
            v=upk2(az[p]); v.x+=__shfl_xor_sync(0xffffffffu,v.x,16); v.y+=__shfl_xor_sync(0xffffffffu,v.y,16); az[p]=pk2(v.x,v.y);
            v=upk2(an[p]); v.x+=__shfl_xor_sync(0xffffffffu,v.x,16); v.y+=__shfl_xor_sync(0xffffffffu,v.y,16); an[p]=pk2(v.x,v.y);
        }
        // prefetch x for next step (overlaps with activation tail)
        float nxr[4],nxz[4],nxn[4];
        if (s+1 < T_){
            const int tt2 = dir ? (T_-2-s) : (s+1);
            const float* prow = P + ((size_t)tt2*B_ + b0)*G3;
            #pragma unroll
            for (int j=0;j<4;j++){
                int bi = half*4 + j;
                nxr[j]=prow[bi*G3+t]; nxz[j]=prow[bi*G3+H_+t]; nxn[j]=prow[bi*G3+2*H_+t];
            }
        }
        // activations for this half's 4 batches (pairs half*2, half*2+1)
        ull cr[2],cz[2],cn[2];
        if (half==0){ cr[0]=ar[0];cr[1]=ar[1];cz[0]=az[0];cz[1]=az[1];cn[0]=an[0];cn[1]=an[1]; }
        else        { cr[0]=ar[2];cr[1]=ar[3];cz[0]=az[2];cz[1]=az[3];cn[0]=an[2];cn[1]=an[3]; }
        float* hnxt = hsA + (cur^1)*1024;
        #pragma unroll
        for (int j=0;j<4;j++){
            int bi = half*4 + j;
            float2 gr=upk2(cr[j>>1]), gz=upk2(cz[j>>1]), gn=upk2(cn[j>>1]);
            float grv=(j&1)?gr.y:gr.x, gzv=(j&1)?gz.y:gz.x, gnv=(j&1)?gn.y:gn.x;
            float rg = fsigm(xr[j] + grv + br);
            float zg = fsigm(xz[j] + gzv + bz);
            float ng = ftanh(xn[j] + rg*(gnv + bn2));
            float h2 = (1.f-zg)*ng + zg*hreg[j];
            hreg[j]=h2; hnxt[t*8+bi]=h2;
            g_f[((size_t)tt*B_ + (b0+bi))*D_ + dir*H_ + t] = h2;
        }
        __syncthreads();
        cur ^= 1;
        #pragma unroll
        for (int j=0;j<4;j++){ xr[j]=nxr[j]; xz[j]=nxz[j]; xn[j]=nxn[j]; }
    }
    #pragma unroll
    for (int j=0;j<4;j++){
        int bi = half*4 + j;
        outH[(size_t)dir*B_*H_ + (size_t)(b0+bi)*H_ + t] = hreg[j];
    }
}

// ============ K3: HMMA bf16-split, tanh epilogue fused with row reductions ============
#define K3_SMEM (2*24576 + 2048)

__global__ __launch_bounds__(256,2) void k3_mma(
    const float* __restrict__ AW, const float* __restrict__ Ab, const float* __restrict__ cent)
{
    extern __shared__ char smem[];
    const unsigned sb = smem_u32(smem);
    const int tid = threadIdx.x;
    const int wid = tid >> 5, lane = tid & 31;
    const int bm = blockIdx.x*128, bn = blockIdx.y*128;
    const int wm = wid >> 1, wn = wid & 1;
    const int lrow = lane & 15;
    const unsigned lk = (lane >> 4) * 16;
    const int r = tid >> 1, kh = (tid & 1) * 8;
    const float* arow = g_f + (size_t)(bm+r)*D_;
    const float* wrow = AW + (size_t)(bn+r)*D_;
    const unsigned soff = (unsigned)(r*48 + kh*2);

    float acc[2][8][4];
    #pragma unroll
    for (int i=0;i<2;i++)
        #pragma unroll
        for (int j=0;j<8;j++)
            #pragma unroll
            for (int q=0;q<4;q++) acc[i][j][q]=0.f;

    float s3p = 0.f;
    float4 av0,av1,bv0,bv1;
    {
        av0 = *(const float4*)(arow+kh); av1 = *(const float4*)(arow+kh+4);
        bv0 = *(const float4*)(wrow+kh); bv1 = *(const float4*)(wrow+kh+4);
        s3p += av0.x*av0.x+av0.y*av0.y+av0.z*av0.z+av0.w*av0.w
             + av1.x*av1.x+av1.y*av1.y+av1.z*av1.z+av1.w*av1.w;
        unsigned ah0=bfp(av0.x,av0.y), ah1=bfp(av0.z,av0.w), ah2=bfp(av1.x,av1.y), ah3=bfp(av1.z,av1.w);
        unsigned bh0=bfp(bv0.x,bv0.y), bh1=bfp(bv0.z,bv0.w), bh2=bfp(bv1.x,bv1.y), bh3=bfp(bv1.z,bv1.w);
        sts128(sb + soff,          ah0,ah1,ah2,ah3);
        sts128(sb + 6144u + soff,  lo_from(av0.x,av0.y,ah0), lo_from(av0.z,av0.w,ah1), lo_from(av1.x,av1.y,ah2), lo_from(av1.z,av1.w,ah3));
        sts128(sb + 12288u + soff, bh0,bh1,bh2,bh3);
        sts128(sb + 18432u + soff, lo_from(bv0.x,bv0.y,bh0), lo_from(bv0.z,bv0.w,bh1), lo_from(bv1.x,bv1.y,bh2), lo_from(bv1.z,bv1.w,bh3));
    }
    __syncthreads();

    for (int kt=0; kt<16; kt++){
        const unsigned base = sb + (unsigned)(kt & 1)*K1_STG;
        const unsigned nbase = sb + (unsigned)((kt & 1)^1)*K1_STG;
        if (kt < 15){
            const int col = (kt+1)*16 + kh;
            av0 = *(const float4*)(arow+col);   av1 = *(const float4*)(arow+col+4);
            bv0 = *(const float4*)(wrow+col);   bv1 = *(const float4*)(wrow+col+4);
            s3p += av0.x*av0.x+av0.y*av0.y+av0.z*av0.z+av0.w*av0.w
                 + av1.x*av1.x+av1.y*av1.y+av1.z*av1.z+av1.w*av1.w;
        }
        unsigned ahi[2][4], alo[2][4];
        #pragma unroll
        for (int mi=0; mi<2; mi++){
            unsigned ad = base + (unsigned)((wm*32 + mi*16 + lrow)*48) + lk;
            ldsm4(ahi[mi], ad);
            ldsm4(alo[mi], ad + 6144u);
        }
        #pragma unroll
        for (int np=0; np<4; np++){
            unsigned bd = base + 12288u + (unsigned)((wn*64 + np*16 + lrow)*48) + lk;
            unsigned bh[4], bl[4];
            ldsm4(bh, bd);
            ldsm4(bl, bd + 6144u);
            #pragma unroll
            for (int mi=0; mi<2; mi++){
                mma16816(acc[mi][2*np],   ahi[mi], bh[0], bh[2]);
                mma16816(acc[mi][2*np+1], ahi[mi], bh[1], bh[3]);
                mma16816(acc[mi][2*np],   alo[mi], bh[0], bh[2]);
                mma16816(acc[mi][2*np+1], alo[mi], bh[1], bh[3]);
                mma16816(acc[mi][2*np],   ahi[mi], bl[0], bl[2]);
                mma16816(acc[mi][2*np+1], ahi[mi], bl[1], bl[3]);
            }
        }
        if (kt < 15){
            unsigned ah0=bfp(av0.x,av0.y), ah1=bfp(av0.z,av0.w), ah2=bfp(av1.x,av1.y), ah3=bfp(av1.z,av1.w);
            unsigned bh0=bfp(bv0.x,bv0.y), bh1=bfp(bv0.z,bv0.w), bh2=bfp(bv1.x,bv1.y), bh3=bfp(bv1.z,bv1.w);
            sts128(nbase + soff,          ah0,ah1,ah2,ah3);
            sts128(nbase + 6144u + soff,  lo_from(av0.x,av0.y,ah0), lo_from(av0.z,av0.w,ah1), lo_from(av1.x,av1.y,ah2), lo_from(av1.z,av1.w,ah3));
            sts128(nbase + 12288u + soff, bh0,bh1,bh2,bh3);
            sts128(nbase + 18432u + soff, lo_from(bv0.x,bv0.y,bh0), lo_from(bv0.z,bv0.w,bh1), lo_from(bv1.x,bv1.y,bh2), lo_from(bv1.z,bv1.w,bh3));
        }
        __syncthreads();
    }

    if (blockIdx.y == 0){
        float s3 = s3p + __shfl_xor_sync(0xffffffffu, s3p, 1);
        if ((tid&1)==0) g_s3[bm+r] = s3;
    }

    float* sp = (float*)smem;
    const int g = lane >> 2, tg = (lane & 3)*2;
    float cv[16], bvv[16];
    #pragma unroll
    for (int ni=0; ni<8; ni++){
        const int c = bn + wn*64 + ni*8 + tg;
        bvv[2*ni]=Ab[c]; bvv[2*ni+1]=Ab[c+1];
        cv[2*ni]=cent[c]; cv[2*ni+1]=cent[c+1];
    }
    #pragma unroll
    for (int mi=0; mi<2; mi++){
        float p1a=0.f,p2a=0.f,p1b=0.f,p2b=0.f;
        #pragma unroll
        for (int ni=0; ni<8; ni++){
            float h0 = ftanh(acc[mi][ni][0]+bvv[2*ni]);
            float h1 = ftanh(acc[mi][ni][1]+bvv[2*ni+1]);
            p1a += h0*cv[2*ni]+h1*cv[2*ni+1]; p2a += h0*h0+h1*h1;
            float h2 = ftanh(acc[mi][ni][2]+bvv[2*ni]);
            float h3 = ftanh(acc[mi][ni][3]+bvv[2*ni+1]);
            p1b += h2*cv[2*ni]+h3*cv[2*ni+1]; p2b += h2*h2+h3*h3;
        }
        #pragma unroll
        for (int o=1; o<=2; o<<=1){
            p1a += __shfl_xor_sync(0xffffffffu,p1a,o);
            p2a += __shfl_xor_sync(0xffffffffu,p2a,o);
            p1b += __shfl_xor_sync(0xffffffffu,p1b,o);
            p2b += __shfl_xor_sync(0xffffffffu,p2b,o);
        }
        if ((lane&3)==0){
            int lr = wm*32 + mi*16 + g;
            sp[lr*2+wn] = p1a;        sp[256 + lr*2+wn] = p2a;
            sp[(lr+8)*2+wn] = p1b;    sp[256 + (lr+8)*2+wn] = p2b;
        }
    }
    __syncthreads();
    if (tid < 128){
        g_s1p[(size_t)blockIdx.y*M_ + bm + tid] = sp[tid*2] + sp[tid*2+1];
        g_s2p[(size_t)blockIdx.y*M_ + bm + tid] = sp[256+tid*2] + sp[256+tid*2+1];
    }
}

// ================= K4: per-row finalize =================
__global__ __launch_bounds__(256) void k4_fin(const float* __restrict__ cent, const float* __restrict__ beta)
{
    __shared__ float swr[8];
    __shared__ float s_cu, s_suru, s_b;
    const int tid = threadIdx.x;
    { float c = cent[tid]; float v=c*c;
      #pragma unroll
      for (int o=16;o;o>>=1) v += __shfl_xor_sync(0xffffffffu, v, o);
      if ((tid&31)==0) swr[tid>>5]=v; }
    __syncthreads();
    if (tid==0){
        float s=0;
        #pragma unroll
        for (int i=0;i<8;i++) s+=swr[i];
        float ru = sqrtf(s);
        s_cu = coshf(ru); s_suru = sinhf(ru)/ru; s_b = beta[0];
    }
    __syncthreads();
    const size_t m = (size_t)blockIdx.x*256 + tid;
    float s1 = g_s1p[m] + g_s1p[M_+m];
    float s2 = g_s2p[m] + g_s2p[M_+m];
    float s3 = g_s3[m];
    float rr = sqrtf(s2);
    float x = coshf(rr)*s_cu - (sinhf(rr)/rr)*s_suru*s1;
    x = fminf(fmaxf(x, 1.f+1e-7f), 1e16f);
    float dist = logf(x) + log1pf(sqrtf(x*x - 1.f + 1e-7f)/x);
    float rf = sqrtf(s3);
    float th = tanhf(rf);
    float gsq = 1.f - th*th;
    gsq = fminf(fmaxf(gsq, 1e-7f), 1.f-1e-7f);
    float gam = 1.f/sqrtf(gsq);
    gam = fminf(fmaxf(gam, 1.f+1e-7f), 1e16f);
    g_coef[m] = expf(-s_b*dist)*gam;
    g_q[m] = th/rf;
}

// ================= K5: pooling =================
__global__ __launch_bounds__(256) void k5_pool(float* __restrict__ out)
{
    __shared__ float cq[T_];
    __shared__ float sden;
    const int b = blockIdx.x, tid = threadIdx.x;
    if (tid < T_) cq[tid] = g_coef[tid*B_ + b];
    __syncthreads();
    if (tid==0){ float s=0; for (int t2=0;t2<T_;t2++) s+=cq[t2]; sden=s; }
    __syncthreads();
    if (tid < T_) cq[tid] = cq[tid]*g_q[tid*B_ + b]/sden;
    __syncthreads();
    float acc = 0.f;
    for (int t2=0;t2<T_;t2++)
        acc += cq[t2]*g_f[((size_t)t2*B_ + b)*D_ + tid];
    out[(size_t)b*D_ + tid] = acc;
}

extern "C" void kernel_launch(void* const* d_in, const int* in_sizes, int n_in,
                              void* d_out, int out_size)
{
    const int*   tok  = (const int*)d_in[0];
    const float* hid  = (const float*)d_in[1];
    const float* emb  = (const float*)d_in[2];
    const float* Wif  = (const float*)d_in[3];
    const float* Whf  = (const float*)d_in[4];
    const float* bif  = (const float*)d_in[5];
    const float* bhf  = (const float*)d_in[6];
    const float* Wib  = (const float*)d_in[7];
    const float* Whb  = (const float*)d_in[8];
    const float* bib  = (const float*)d_in[9];
    const float* bhb  = (const float*)d_in[10];
    const float* AW   = (const float*)d_in[11];
    const float* Ab   = (const float*)d_in[12];
    const float* cent = (const float*)d_in[13];
    const float* beta = (const float*)d_in[14];
    float* out = (float*)d_out;

    cudaFuncSetAttribute(k1_mma, cudaFuncAttributeMaxDynamicSharedMemorySize, K1_SMEM);
    cudaFuncSetAttribute(k2_gru, cudaFuncAttributeMaxDynamicSharedMemorySize, K2_SMEM);
    cudaFuncSetAttribute(k3_mma, cudaFuncAttributeMaxDynamicSharedMemorySize, K3_SMEM);

    // 4 dummy launches: shift the fixed ncu capture slot onto k2_gru
    kd_nop<<<1,32>>>(0);
    kd_nop<<<1,32>>>(1);
    kd_nop<<<1,32>>>(2);
    kd_nop<<<1,32>>>(3);

    k1_mma<<<dim3(512,6),256,K1_SMEM>>>(tok, emb, Wif, Wib, bif, bib);
    k2_gru<<<dim3(64,2),256,K2_SMEM>>>(hid, Whf, Whb, bhf, bhb, out + (size_t)B_*D_);
    k3_mma<<<dim3(512,2),256,K3_SMEM>>>(AW, Ab, cent);
    k4_fin<<<256,256>>>(cent, beta);
    k5_pool<<<512,256>>>(out);
}

// round 13
// speedup vs baseline: 2.0292x; 1.0241x over previous
#include <cuda_runtime.h>
#include <cuda_bf16.h>
#include <cstdint>

#define T_ 128
#define B_ 512
#define H_ 128
#define EMBD 300
#define D_ 256
#define G3 384
#define M_ (T_*B_)

__device__ float g_Pf[(size_t)M_*G3];
__device__ float g_Pb[(size_t)M_*G3];
__device__ float g_f[(size_t)M_*D_];
__device__ float g_s1p[2*M_];
__device__ float g_s2p[2*M_];
__device__ float g_s3[M_];
__device__ float g_coef[M_];
__device__ float g_q[M_];

typedef unsigned long long ull;
__device__ __forceinline__ void fma2(ull&c, ull a, ull b){ asm("fma.rn.f32x2 %0,%1,%2,%0;":"+l"(c):"l"(a),"l"(b)); }
__device__ __forceinline__ ull pk2(float lo,float hi){ ull r; asm("mov.b64 %0,{%1,%2};":"=l"(r):"f"(lo),"f"(hi)); return r; }
__device__ __forceinline__ float2 upk2(ull v){ float2 r; asm("mov.b64 {%0,%1},%2;":"=f"(r.x),"=f"(r.y):"l"(v)); return r; }
__device__ __forceinline__ float fsigm(float x){ return __fdividef(1.f, 1.f + __expf(-x)); }
__device__ __forceinline__ float ftanh(float x){ float e = __expf(2.f*x); return 1.f - __fdividef(2.f, e + 1.f); }

__device__ __forceinline__ unsigned smem_u32(const void* p){
    unsigned a; asm("{ .reg .u64 t; cvta.to.shared.u64 t, %1; cvt.u32.u64 %0, t; }":"=r"(a):"l"(p)); return a;
}
__device__ __forceinline__ unsigned bfp(float a, float b){ unsigned r; asm("cvt.rn.bf16x2.f32 %0,%1,%2;":"=r"(r):"f"(b),"f"(a)); return r; }
__device__ __forceinline__ unsigned lo_from(float a, float b, unsigned hp){
    float ha = __uint_as_float(hp << 16);
    float hb = __uint_as_float(hp & 0xffff0000u);
    return bfp(a - ha, b - hb);
}
__device__ __forceinline__ void sts128(unsigned addr, unsigned x, unsigned y, unsigned z, unsigned w){
    asm volatile("st.shared.v4.b32 [%0], {%1,%2,%3,%4};"::"r"(addr),"r"(x),"r"(y),"r"(z),"r"(w):"memory");
}
__device__ __forceinline__ void ldsm4(unsigned* r, unsigned addr){
    asm volatile("ldmatrix.sync.aligned.m8n8.x4.shared.b16 {%0,%1,%2,%3}, [%4];"
        : "=r"(r[0]),"=r"(r[1]),"=r"(r[2]),"=r"(r[3]) : "r"(addr));
}
__device__ __forceinline__ void mma16816(float* d, const unsigned* a, unsigned b0, unsigned b1){
    asm volatile("mma.sync.aligned.m16n8k16.row.col.f32.bf16.bf16.f32 "
        "{%0,%1,%2,%3}, {%4,%5,%6,%7}, {%8,%9}, {%0,%1,%2,%3};"
        : "+f"(d[0]),"+f"(d[1]),"+f"(d[2]),"+f"(d[3])
        : "r"(a[0]),"r"(a[1]),"r"(a[2]),"r"(a[3]), "r"(b0),"r"(b1));
}

// ================= K1: HMMA bf16-split GEMM =================
#define K1_STG 24576u
#define K1_SMEM (2*24576 + 512)

__global__ __launch_bounds__(256,2) void k1_mma(
    const int* __restrict__ tok, const float* __restrict__ emb,
    const float* __restrict__ Wf, const float* __restrict__ Wb,
    const float* __restrict__ bf, const float* __restrict__ bb)
{
    extern __shared__ char smem[];
    const unsigned sb = smem_u32(smem);
    int* toks = (int*)(smem + 2*24576);
    const int tid = threadIdx.x;
    const int wid = tid >> 5, lane = tid & 31;
    const int bm = blockIdx.x*128, bn = blockIdx.y*128;
    if (tid < 128) toks[tid] = tok[bm + tid];
    __syncthreads();

    const int wm = wid >> 1, wn = wid & 1;
    const int lrow = lane & 15;
    const unsigned lk = (lane >> 4) * 16;
    const int r = tid >> 1, kh = (tid & 1) * 8;
    const float* arow = emb + (size_t)toks[r]*EMBD;
    const int ng = bn + r;
    const float* wrow = (ng < G3) ? (Wf + (size_t)ng*EMBD) : (Wb + (size_t)(ng-G3)*EMBD);
    const unsigned soff = (unsigned)(r*48 + kh*2);

    float acc[2][8][4];
    #pragma unroll
    for (int i=0;i<2;i++)
        #pragma unroll
        for (int j=0;j<8;j++)
            #pragma unroll
            for (int q=0;q<4;q++) acc[i][j][q]=0.f;

    float4 av0,av1,bv0,bv1;
    {
        av0 = *(const float4*)(arow+kh); av1 = *(const float4*)(arow+kh+4);
        bv0 = *(const float4*)(wrow+kh); bv1 = *(const float4*)(wrow+kh+4);
        unsigned ah0=bfp(av0.x,av0.y), ah1=bfp(av0.z,av0.w), ah2=bfp(av1.x,av1.y), ah3=bfp(av1.z,av1.w);
        unsigned bh0=bfp(bv0.x,bv0.y), bh1=bfp(bv0.z,bv0.w), bh2=bfp(bv1.x,bv1.y), bh3=bfp(bv1.z,bv1.w);
        sts128(sb + soff,          ah0,ah1,ah2,ah3);
        sts128(sb + 6144u + soff,  lo_from(av0.x,av0.y,ah0), lo_from(av0.z,av0.w,ah1), lo_from(av1.x,av1.y,ah2), lo_from(av1.z,av1.w,ah3));
        sts128(sb + 12288u + soff, bh0,bh1,bh2,bh3);
        sts128(sb + 18432u + soff, lo_from(bv0.x,bv0.y,bh0), lo_from(bv0.z,bv0.w,bh1), lo_from(bv1.x,bv1.y,bh2), lo_from(bv1.z,bv1.w,bh3));
    }
    __syncthreads();

    for (int kt=0; kt<19; kt++){
        const unsigned base = sb + (unsigned)(kt & 1)*K1_STG;
        const unsigned nbase = sb + (unsigned)((kt & 1)^1)*K1_STG;
        if (kt < 18){
            const int col = (kt+1)*16 + kh;
            const float4 z4 = make_float4(0.f,0.f,0.f,0.f);
            av0 = (col   < EMBD) ? *(const float4*)(arow+col)   : z4;
            av1 = (col+4 < EMBD) ? *(const float4*)(arow+col+4) : z4;
            bv0 = (col   < EMBD) ? *(const float4*)(wrow+col)   : z4;
            bv1 = (col+4 < EMBD) ? *(const float4*)(wrow+col+4) : z4;
        }
        unsigned ahi[2][4], alo[2][4];
        #pragma unroll
        for (int mi=0; mi<2; mi++){
            unsigned ad = base + (unsigned)((wm*32 + mi*16 + lrow)*48) + lk;
            ldsm4(ahi[mi], ad);
            ldsm4(alo[mi], ad + 6144u);
        }
        #pragma unroll
        for (int np=0; np<4; np++){
            unsigned bd = base + 12288u + (unsigned)((wn*64 + np*16 + lrow)*48) + lk;
            unsigned bh[4], bl[4];
            ldsm4(bh, bd);
            ldsm4(bl, bd + 6144u);
            #pragma unroll
            for (int mi=0; mi<2; mi++){
                mma16816(acc[mi][2*np],   ahi[mi], bh[0], bh[2]);
                mma16816(acc[mi][2*np+1], ahi[mi], bh[1], bh[3]);
                mma16816(acc[mi][2*np],   alo[mi], bh[0], bh[2]);
                mma16816(acc[mi][2*np+1], alo[mi], bh[1], bh[3]);
                mma16816(acc[mi][2*np],   ahi[mi], bl[0], bl[2]);
                mma16816(acc[mi][2*np+1], ahi[mi], bl[1], bl[3]);
            }
        }
        if (kt < 18){
            unsigned ah0=bfp(av0.x,av0.y), ah1=bfp(av0.z,av0.w), ah2=bfp(av1.x,av1.y), ah3=bfp(av1.z,av1.w);
            unsigned bh0=bfp(bv0.x,bv0.y), bh1=bfp(bv0.z,bv0.w), bh2=bfp(bv1.x,bv1.y), bh3=bfp(bv1.z,bv1.w);
            sts128(nbase + soff,          ah0,ah1,ah2,ah3);
            sts128(nbase + 6144u + soff,  lo_from(av0.x,av0.y,ah0), lo_from(av0.z,av0.w,ah1), lo_from(av1.x,av1.y,ah2), lo_from(av1.z,av1.w,ah3));
            sts128(nbase + 12288u + soff, bh0,bh1,bh2,bh3);
            sts128(nbase + 18432u + soff, lo_from(bv0.x,bv0.y,bh0), lo_from(bv0.z,bv0.w,bh1), lo_from(bv1.x,bv1.y,bh2), lo_from(bv1.z,bv1.w,bh3));
        }
        __syncthreads();
    }

    float* dst; const float* bias_; int nb;
    if (bn < G3){ dst = g_Pf; nb = bn; bias_ = bf; } else { dst = g_Pb; nb = bn - G3; bias_ = bb; }
    const int g = lane >> 2, tg = (lane & 3)*2;
    #pragma unroll
    for (int mi=0; mi<2; mi++){
        const int row = bm + wm*32 + mi*16 + g;
        #pragma unroll
        for (int ni=0; ni<8; ni++){
            const int c = wn*64 + ni*8 + tg;
            const float b0 = bias_[nb + c], b1 = bias_[nb + c + 1];
            float2 v0 = make_float2(acc[mi][ni][0] + b0, acc[mi][ni][1] + b1);
            float2 v1 = make_float2(acc[mi][ni][2] + b0, acc[mi][ni][3] + b1);
            *(float2*)(dst + (size_t)row*G3 + nb + c) = v0;
            *(float2*)(dst + (size_t)(row+8)*G3 + nb + c) = v1;
        }
    }
}

// ===== K2: GRU, grid(64,2), 512 threads. In-warp 4-quarter k-split (shfl butterfly), =====
// ===== skewed smem (bank-conflict-free), double-buffered h, ONE barrier/step.        =====
// floats: wrz(float2) @0 (32832f), wn @32832 (16416f), hs[2][1056] @49248. 51360f = 205440B
#define K2_SMEM (51360*4)

__global__ __launch_bounds__(512) void k2_gru(
    const float* __restrict__ hidden,
    const float* __restrict__ Whf, const float* __restrict__ Whb,
    const float* __restrict__ bhf, const float* __restrict__ bhb,
    float* __restrict__ outH)
{
    extern __shared__ float sm[];
    float2* wrz = (float2*)sm;           // idx: k*128 + (k>>5)*8 + t
    float*  wnm = sm + 32832;            // idx: k*128 + (k>>5)*8 + t
    float*  hsA = sm + 49248;            // [2][1056], idx: k*8 + (k>>5)*8 + bi

    const int dir = blockIdx.y, b0 = blockIdx.x*8;
    const int tid = threadIdx.x;
    const int lane = tid & 31, wid = tid >> 5;
    const int t = wid*8 + (lane & 7);    // hidden index (0..127)
    const int q = lane >> 3;             // k-quarter (0..3); also owns batches 2q, 2q+1
    const int kbase = q*32;
    const float* W  = dir? Whb : Whf;
    const float* bh = dir? bhb : bhf;
    const float* P  = dir? g_Pb : g_Pf;

    for (int idx = tid; idx < 128*G3; idx += 512){
        int j = idx >> 7, k = idx & 127;
        float w = W[(size_t)j*H_ + k];
        int sk = k*128 + ((k>>5)<<3);
        if (j < 128)      ((float*)wrz)[(sk + j)*2]         = w;
        else if (j < 256) ((float*)wrz)[(sk + (j-128))*2+1] = w;
        else              wnm[sk + (j-256)] = w;
    }
    const int hwidx = t*8 + ((t>>5)<<3);  // skewed h index base for writer (k == t)
    float hreg[2];
    {
        float h0 = hidden[(size_t)dir*B_*H_ + (size_t)(b0+2*q)*H_ + t];
        float h1 = hidden[(size_t)dir*B_*H_ + (size_t)(b0+2*q+1)*H_ + t];
        hreg[0]=h0; hreg[1]=h1;
        *(float2*)(hsA + hwidx + 2*q) = make_float2(h0,h1);
    }
    const float br=bh[t], bz=bh[H_+t], bn2=bh[2*H_+t];

    float xr[2],xz[2],xn[2];
    {
        const int tt0 = dir ? (T_-1) : 0;
        const float* prow = P + ((size_t)tt0*B_ + b0 + 2*q)*G3;
        xr[0]=prow[t]; xz[0]=prow[H_+t]; xn[0]=prow[2*H_+t];
        xr[1]=prow[G3+t]; xz[1]=prow[G3+H_+t]; xn[1]=prow[G3+2*H_+t];
    }
    __syncthreads();

    int cur = 0;
    for (int s=0;s<T_;s++){
        const int tt = dir ? (T_-1-s) : s;
        const longlong2* h128 = (const longlong2*)(hsA + cur*1056);
        ull ar[4],az[4],an[4];
        #pragma unroll
        for (int p=0;p<4;p++){ ar[p]=0; az[p]=0; an[p]=0; }
        #pragma unroll 4
        for (int k=kbase; k<kbase+32; k++){
            const int sk = k*128 + q*8 + t;      // (k>>5)==q in this quarter
            float2 wv = wrz[sk];
            float wnv = wnm[sk];
            ull p0=pk2(wv.x,wv.x), p1=pk2(wv.y,wv.y), p2=pk2(wnv,wnv);
            longlong2 hA = h128[2*k + 2*q], hB = h128[2*k + 2*q + 1];
            ull h0=(ull)hA.x, h1=(ull)hA.y, h2=(ull)hB.x, h3=(ull)hB.y;
            fma2(ar[0],h0,p0); fma2(ar[1],h1,p0); fma2(ar[2],h2,p0); fma2(ar[3],h3,p0);
            fma2(az[0],h0,p1); fma2(az[1],h1,p1); fma2(az[2],h2,p1); fma2(az[3],h3,p1);
            fma2(an[0],h0,p2); fma2(an[1],h1,p2); fma2(an[2],h2,p2); fma2(an[3],h3,p2);
        }
        // butterfly combine across quarters (xor 8, xor 16): full sums in all pairs
        #pragma unroll
        for (int p=0;p<4;p++){
            float2 v;
            v=upk2(ar[p]);
            v.x+=__shfl_xor_sync(0xffffffffu,v.x,8);  v.y+=__shfl_xor_sync(0xffffffffu,v.y,8);
            v.x+=__shfl_xor_sync(0xffffffffu,v.x,16); v.y+=__shfl_xor_sync(0xffffffffu,v.y,16);
            ar[p]=pk2(v.x,v.y);
            v=upk2(az[p]);
            v.x+=__shfl_xor_sync(0xffffffffu,v.x,8);  v.y+=__shfl_xor_sync(0xffffffffu,v.y,8);
            v.x+=__shfl_xor_sync(0xffffffffu,v.x,16); v.y+=__shfl_xor_sync(0xffffffffu,v.y,16);
            az[p]=pk2(v.x,v.y);
            v=upk2(an[p]);
            v.x+=__shfl_xor_sync(0xffffffffu,v.x,8);  v.y+=__shfl_xor_sync(0xffffffffu,v.y,8);
            v.x+=__shfl_xor_sync(0xffffffffu,v.x,16); v.y+=__shfl_xor_sync(0xffffffffu,v.y,16);
            an[p]=pk2(v.x,v.y);
        }
        // prefetch x for next step
        float nxr[2]={0,0},nxz[2]={0,0},nxn[2]={0,0};
        if (s+1 < T_){
            const int tt2 = dir ? (T_-2-s) : (s+1);
            const float* prow = P + ((size_t)tt2*B_ + b0 + 2*q)*G3;
            nxr[0]=prow[t]; nxz[0]=prow[H_+t]; nxn[0]=prow[2*H_+t];
            nxr[1]=prow[G3+t]; nxz[1]=prow[G3+H_+t]; nxn[1]=prow[G3+2*H_+t];
        }
        // select this quarter's batch pair
        ull cr = (q&2) ? ((q&1)? ar[3]:ar[2]) : ((q&1)? ar[1]:ar[0]);
        ull cz = (q&2) ? ((q&1)? az[3]:az[2]) : ((q&1)? az[1]:az[0]);
        ull cn = (q&2) ? ((q&1)? an[3]:an[2]) : ((q&1)? an[1]:an[0]);
        float2 gr=upk2(cr), gz=upk2(cz), gn=upk2(cn);
        float* hnxt = hsA + (cur^1)*1056;
        float h2v[2];
        #pragma unroll
        for (int j=0;j<2;j++){
            float grv=j?gr.y:gr.x, gzv=j?gz.y:gz.x, gnv=j?gn.y:gn.x;
            float rg = fsigm(xr[j] + grv + br);
            float zg = fsigm(xz[j] + gzv + bz);
            float ng = ftanh(xn[j] + rg*(gnv + bn2));
            float h2 = (1.f-zg)*ng + zg*hreg[j];
            hreg[j]=h2; h2v[j]=h2;
            g_f[((size_t)tt*B_ + (b0+2*q+j))*D_ + dir*H_ + t] = h2;
        }
        *(float2*)(hnxt + hwidx + 2*q) = make_float2(h2v[0],h2v[1]);
        __syncthreads();
        cur ^= 1;
        #pragma unroll
        for (int j=0;j<2;j++){ xr[j]=nxr[j]; xz[j]=nxz[j]; xn[j]=nxn[j]; }
    }
    outH[(size_t)dir*B_*H_ + (size_t)(b0+2*q)*H_ + t]   = hreg[0];
    outH[(size_t)dir*B_*H_ + (size_t)(b0+2*q+1)*H_ + t] = hreg[1];
}

// ============ K3: HMMA bf16-split, tanh epilogue fused with row reductions ============
#define K3_SMEM (2*24576 + 2048)

__global__ __launch_bounds__(256,2) void k3_mma(
    const float* __restrict__ AW, const float* __restrict__ Ab, const float* __restrict__ cent)
{
    extern __shared__ char smem[];
    const unsigned sb = smem_u32(smem);
    const int tid = threadIdx.x;
    const int wid = tid >> 5, lane = tid & 31;
    const int bm = blockIdx.x*128, bn = blockIdx.y*128;
    const int wm = wid >> 1, wn = wid & 1;
    const int lrow = lane & 15;
    const unsigned lk = (lane >> 4) * 16;
    const int r = tid >> 1, kh = (tid & 1) * 8;
    const float* arow = g_f + (size_t)(bm+r)*D_;
    const float* wrow = AW + (size_t)(bn+r)*D_;
    const unsigned soff = (unsigned)(r*48 + kh*2);

    float acc[2][8][4];
    #pragma unroll
    for (int i=0;i<2;i++)
        #pragma unroll
        for (int j=0;j<8;j++)
            #pragma unroll
            for (int q=0;q<4;q++) acc[i][j][q]=0.f;

    float s3p = 0.f;
    float4 av0,av1,bv0,bv1;
    {
        av0 = *(const float4*)(arow+kh); av1 = *(const float4*)(arow+kh+4);
        bv0 = *(const float4*)(wrow+kh); bv1 = *(const float4*)(wrow+kh+4);
        s3p += av0.x*av0.x+av0.y*av0.y+av0.z*av0.z+av0.w*av0.w
             + av1.x*av1.x+av1.y*av1.y+av1.z*av1.z+av1.w*av1.w;
        unsigned ah0=bfp(av0.x,av0.y), ah1=bfp(av0.z,av0.w), ah2=bfp(av1.x,av1.y), ah3=bfp(av1.z,av1.w);
        unsigned bh0=bfp(bv0.x,bv0.y), bh1=bfp(bv0.z,bv0.w), bh2=bfp(bv1.x,bv1.y), bh3=bfp(bv1.z,bv1.w);
        sts128(sb + soff,          ah0,ah1,ah2,ah3);
        sts128(sb + 6144u + soff,  lo_from(av0.x,av0.y,ah0), lo_from(av0.z,av0.w,ah1), lo_from(av1.x,av1.y,ah2), lo_from(av1.z,av1.w,ah3));
        sts128(sb + 12288u + soff, bh0,bh1,bh2,bh3);
        sts128(sb + 18432u + soff, lo_from(bv0.x,bv0.y,bh0), lo_from(bv0.z,bv0.w,bh1), lo_from(bv1.x,bv1.y,bh2), lo_from(bv1.z,bv1.w,bh3));
    }
    __syncthreads();

    for (int kt=0; kt<16; kt++){
        const unsigned base = sb + (unsigned)(kt & 1)*K1_STG;
        const unsigned nbase = sb + (unsigned)((kt & 1)^1)*K1_STG;
        if (kt < 15){
            const int col = (kt+1)*16 + kh;
            av0 = *(const float4*)(arow+col);   av1 = *(const float4*)(arow+col+4);
            bv0 = *(const float4*)(wrow+col);   bv1 = *(const float4*)(wrow+col+4);
            s3p += av0.x*av0.x+av0.y*av0.y+av0.z*av0.z+av0.w*av0.w
                 + av1.x*av1.x+av1.y*av1.y+av1.z*av1.z+av1.w*av1.w;
        }
        unsigned ahi[2][4], alo[2][4];
        #pragma unroll
        for (int mi=0; mi<2; mi++){
            unsigned ad = base + (unsigned)((wm*32 + mi*16 + lrow)*48) + lk;
            ldsm4(ahi[mi], ad);
            ldsm4(alo[mi], ad + 6144u);
        }
        #pragma unroll
        for (int np=0; np<4; np++){
            unsigned bd = base + 12288u + (unsigned)((wn*64 + np*16 + lrow)*48) + lk;
            unsigned bh[4], bl[4];
            ldsm4(bh, bd);
            ldsm4(bl, bd + 6144u);
            #pragma unroll
            for (int mi=0; mi<2; mi++){
                mma16816(acc[mi][2*np],   ahi[mi], bh[0], bh[2]);
                mma16816(acc[mi][2*np+1], ahi[mi], bh[1], bh[3]);
                mma16816(acc[mi][2*np],   alo[mi], bh[0], bh[2]);
                mma16816(acc[mi][2*np+1], alo[mi], bh[1], bh[3]);
                mma16816(acc[mi][2*np],   ahi[mi], bl[0], bl[2]);
                mma16816(acc[mi][2*np+1], ahi[mi], bl[1], bl[3]);
            }
        }
        if (kt < 15){
            unsigned ah0=bfp(av0.x,av0.y), ah1=bfp(av0.z,av0.w), ah2=bfp(av1.x,av1.y), ah3=bfp(av1.z,av1.w);
            unsigned bh0=bfp(bv0.x,bv0.y), bh1=bfp(bv0.z,bv0.w), bh2=bfp(bv1.x,bv1.y), bh3=bfp(bv1.z,bv1.w);
            sts128(nbase + soff,          ah0,ah1,ah2,ah3);
            sts128(nbase + 6144u + soff,  lo_from(av0.x,av0.y,ah0), lo_from(av0.z,av0.w,ah1), lo_from(av1.x,av1.y,ah2), lo_from(av1.z,av1.w,ah3));
            sts128(nbase + 12288u + soff, bh0,bh1,bh2,bh3);
            sts128(nbase + 18432u + soff, lo_from(bv0.x,bv0.y,bh0), lo_from(bv0.z,bv0.w,bh1), lo_from(bv1.x,bv1.y,bh2), lo_from(bv1.z,bv1.w,bh3));
        }
        __syncthreads();
    }

    if (blockIdx.y == 0){
        float s3 = s3p + __shfl_xor_sync(0xffffffffu, s3p, 1);
        if ((tid&1)==0) g_s3[bm+r] = s3;
    }

    float* sp = (float*)smem;
    const int g = lane >> 2, tg = (lane & 3)*2;
    float cv[16], bvv[16];
    #pragma unroll
    for (int ni=0; ni<8; ni++){
        const int c = bn + wn*64 + ni*8 + tg;
        bvv[2*ni]=Ab[c]; bvv[2*ni+1]=Ab[c+1];
        cv[2*ni]=cent[c]; cv[2*ni+1]=cent[c+1];
    }
    #pragma unroll
    for (int mi=0; mi<2; mi++){
        float p1a=0.f,p2a=0.f,p1b=0.f,p2b=0.f;
        #pragma unroll
        for (int ni=0; ni<8; ni++){
            float h0 = ftanh(acc[mi][ni][0]+bvv[2*ni]);
            float h1 = ftanh(acc[mi][ni][1]+bvv[2*ni+1]);
            p1a += h0*cv[2*ni]+h1*cv[2*ni+1]; p2a += h0*h0+h1*h1;
            float h2 = ftanh(acc[mi][ni][2]+bvv[2*ni]);
            float h3 = ftanh(acc[mi][ni][3]+bvv[2*ni+1]);
            p1b += h2*cv[2*ni]+h3*cv[2*ni+1]; p2b += h2*h2+h3*h3;
        }
        #pragma unroll
        for (int o=1; o<=2; o<<=1){
            p1a += __shfl_xor_sync(0xffffffffu,p1a,o);
            p2a += __shfl_xor_sync(0xffffffffu,p2a,o);
            p1b += __shfl_xor_sync(0xffffffffu,p1b,o);
            p2b += __shfl_xor_sync(0xffffffffu,p2b,o);
        }
        if ((lane&3)==0){
            int lr = wm*32 + mi*16 + g;
            sp[lr*2+wn] = p1a;        sp[256 + lr*2+wn] = p2a;
            sp[(lr+8)*2+wn] = p1b;    sp[256 + (lr+8)*2+wn] = p2b;
        }
    }
    __syncthreads();
    if (tid < 128){
        g_s1p[(size_t)blockIdx.y*M_ + bm + tid] = sp[tid*2] + sp[tid*2+1];
        g_s2p[(size_t)blockIdx.y*M_ + bm + tid] = sp[256+tid*2] + sp[256+tid*2+1];
    }
}

// ================= K4: per-row finalize =================
__global__ __launch_bounds__(256) void k4_fin(const float* __restrict__ cent, const float* __restrict__ beta)
{
    __shared__ float swr[8];
    __shared__ float s_cu, s_suru, s_b;
    const int tid = threadIdx.x;
    { float c = cent[tid]; float v=c*c;
      #pragma unroll
      for (int o=16;o;o>>=1) v += __shfl_xor_sync(0xffffffffu, v, o);
      if ((tid&31)==0) swr[tid>>5]=v; }
    __syncthreads();
    if (tid==0){
        float s=0;
        #pragma unroll
        for (int i=0;i<8;i++) s+=swr[i];
        float ru = sqrtf(s);
        s_cu = coshf(ru); s_suru = sinhf(ru)/ru; s_b = beta[0];
    }
    __syncthreads();
    const size_t m = (size_t)blockIdx.x*256 + tid;
    float s1 = g_s1p[m] + g_s1p[M_+m];
    float s2 = g_s2p[m] + g_s2p[M_+m];
    float s3 = g_s3[m];
    float rr = sqrtf(s2);
    float x = coshf(rr)*s_cu - (sinhf(rr)/rr)*s_suru*s1;
    x = fminf(fmaxf(x, 1.f+1e-7f), 1e16f);
    float dist = logf(x) + log1pf(sqrtf(x*x - 1.f + 1e-7f)/x);
    float rf = sqrtf(s3);
    float th = tanhf(rf);
    float gsq = 1.f - th*th;
    gsq = fminf(fmaxf(gsq, 1e-7f), 1.f-1e-7f);
    float gam = 1.f/sqrtf(gsq);
    gam = fminf(fmaxf(gam, 1.f+1e-7f), 1e16f);
    g_coef[m] = expf(-s_b*dist)*gam;
    g_q[m] = th/rf;
}

// ================= K5: pooling =================
__global__ __launch_bounds__(256) void k5_pool(float* __restrict__ out)
{
    __shared__ float cq[T_];
    __shared__ float sden;
    const int b = blockIdx.x, tid = threadIdx.x;
    if (tid < T_) cq[tid] = g_coef[tid*B_ + b];
    __syncthreads();
    if (tid==0){ float s=0; for (int t2=0;t2<T_;t2++) s+=cq[t2]; sden=s; }
    __syncthreads();
    if (tid < T_) cq[tid] = cq[tid]*g_q[tid*B_ + b]/sden;
    __syncthreads();
    float acc = 0.f;
    for (int t2=0;t2<T_;t2++)
        acc += cq[t2]*g_f[((size_t)t2*B_ + b)*D_ + tid];
    out[(size_t)b*D_ + tid] = acc;
}

extern "C" void kernel_launch(void* const* d_in, const int* in_sizes, int n_in,
                              void* d_out, int out_size)
{
    const int*   tok  = (const int*)d_in[0];
    const float* hid  = (const float*)d_in[1];
    const float* emb  = (const float*)d_in[2];
    const float* Wif  = (const float*)d_in[3];
    const float* Whf  = (const float*)d_in[4];
    const float* bif  = (const float*)d_in[5];
    const float* bhf  = (const float*)d_in[6];
    const float* Wib  = (const float*)d_in[7];
    const float* Whb  = (const float*)d_in[8];
    const float* bib  = (const float*)d_in[9];
    const float* bhb  = (const float*)d_in[10];
    const float* AW   = (const float*)d_in[11];
    const float* Ab   = (const float*)d_in[12];
    const float* cent = (const float*)d_in[13];
    const float* beta = (const float*)d_in[14];
    float* out = (float*)d_out;

    cudaFuncSetAttribute(k1_mma, cudaFuncAttributeMaxDynamicSharedMemorySize, K1_SMEM);
    cudaFuncSetAttribute(k2_gru, cudaFuncAttributeMaxDynamicSharedMemorySize, K2_SMEM);
    cudaFuncSetAttribute(k3_mma, cudaFuncAttributeMaxDynamicSharedMemorySize, K3_SMEM);

    k1_mma<<<dim3(512,6),256,K1_SMEM>>>(tok, emb, Wif, Wib, bif, bib);
    k2_gru<<<dim3(64,2),512,K2_SMEM>>>(hid, Whf, Whb, bhf, bhb, out + (size_t)B_*D_);
    k3_mma<<<dim3(512,2),256,K3_SMEM>>>(AW, Ab, cent);
    k4_fin<<<256,256>>>(cent, beta);
    k5_pool<<<512,256>>>(out);
}